// round 12
// baseline (speedup 1.0000x reference)
#include <cuda_runtime.h>
#include <math.h>

typedef unsigned long long ull;

namespace {
constexpr int kB = 2, kC = 128, kHd = 64, kWd = 96, kHu = 128, kWu = 192;
constexpr int kN = kB * kHu * kWu;
constexpr int kHWd = kHd * kWd, kHWu = kHu * kWu;
}

__device__ float g_WA[128 * 384];
__device__ float g_WB[128 * 384];

__global__ void prep_kernel(const float* __restrict__ o1w) {
    int i = blockIdx.x * blockDim.x + threadIdx.x;
    if (i < 128 * 384) {
        int in = i / 384, o = i - in * 384;
        float w2 = o1w[(256 + in) * 384 + o];
        g_WA[i] = o1w[in * 384 + o] + w2;
        g_WB[i] = o1w[(128 + in) * 384 + o] - w2;
    }
}

// ---- packed f32x2 (SASS FFMA2, PTX-only) ----
__device__ __forceinline__ ull pk2(float a, float b) {
    ull r; asm("mov.b64 %0,{%1,%2};" : "=l"(r) : "f"(a), "f"(b)); return r;
}
__device__ __forceinline__ ull dup2(float a) { return pk2(a, a); }
__device__ __forceinline__ void up2(ull v, float& a, float& b) {
    asm("mov.b64 {%0,%1},%2;" : "=f"(a), "=f"(b) : "l"(v));
}
__device__ __forceinline__ ull fma2(ull a, ull b, ull c) {
    ull d; asm("fma.rn.f32x2 %0,%1,%2,%3;" : "=l"(d) : "l"(a), "l"(b), "l"(c)); return d;
}
__device__ __forceinline__ ull add2(ull a, ull b) {
    ull d; asm("add.rn.f32x2 %0,%1,%2;" : "=l"(d) : "l"(a), "l"(b)); return d;
}
__device__ __forceinline__ ull mul2(ull a, ull b) {
    ull d; asm("mul.rn.f32x2 %0,%1,%2;" : "=l"(d) : "l"(a), "l"(b)); return d;
}

// 8B-slot smem, XOR swizzle on bits [1:4) (bit0 kept -> 16B pairs stay intact)
__device__ __forceinline__ int swz(int s) { return s ^ ((s >> 4) & 14); }
__device__ __forceinline__ ull ldp(const float* b, int s) {
    return *reinterpret_cast<const ull*>(b + 2 * swz(s));
}
__device__ __forceinline__ void stp(float* b, int s, ull v) {
    *reinterpret_cast<ull*>(b + 2 * swz(s)) = v;
}
__device__ __forceinline__ ulonglong2 ld16(const float* b, int s) {  // s even
    return *reinterpret_cast<const ulonglong2*>(b + 2 * swz(s));
}
__device__ __forceinline__ void st16(float* b, int s, ull x, ull y) {  // s even
    *reinterpret_cast<ulonglong2*>(b + 2 * swz(s)) = make_ulonglong2(x, y);
}

__device__ __forceinline__ ull wsum2(ull v) {
#pragma unroll
    for (int o = 16; o; o >>= 1) v = add2(v, __shfl_xor_sync(0xffffffffu, v, o));
    return v;
}

// LN of 2 independent 128-ch vectors packed as a pair: v[i] = ch (o4+i)
__device__ __forceinline__ void ln2(const ull v[4], float eps, ull o[4]) {
    ull s = add2(add2(v[0], v[1]), add2(v[2], v[3]));
    ull q = fma2(v[0], v[0], fma2(v[1], v[1], fma2(v[2], v[2], mul2(v[3], v[3]))));
    s = wsum2(s); q = wsum2(q);
    float s0, s1, q0, q1; up2(s, s0, s1); up2(q, q0, q1);
    float m0 = s0 * (1.0f / 128.0f), m1 = s1 * (1.0f / 128.0f);
    float r0 = rsqrtf(fmaxf(q0 * (1.0f / 128.0f) - m0 * m0, 0.0f) + eps);
    float r1 = rsqrtf(fmaxf(q1 * (1.0f / 128.0f) - m1 * m1, 0.0f) + eps);
    ull nm = pk2(-m0, -m1), rr = pk2(r0, r1);
#pragma unroll
    for (int i = 0; i < 4; ++i) o[i] = mul2(add2(v[i], nm), rr);
}

// fast tanh-gelu: x * sigmoid(2u), u = 0.79788456(x + 0.044715 x^3)
__device__ __forceinline__ float gelu_t(float x) {
    float x2 = x * x;
    float arg = -1.5957691216057308f * fmaf(0.044715f * x2, x, x);
    return __fdividef(x, 1.0f + __expf(arg));
}
__device__ __forceinline__ ull gelu_t2(ull v) { float a, b; up2(v, a, b); return pk2(gelu_t(a), gelu_t(b)); }
__device__ __forceinline__ float gelu_e(float x) { return 0.5f * x * (1.0f + erff(x * 0.7071067811865475f)); }
__device__ __forceinline__ ull gelu_e2(ull v) { float a, b; up2(v, a, b); return pk2(gelu_e(a), gelu_e(b)); }

__device__ __forceinline__ float4 ldg4(const float* p) {
    return __ldg(reinterpret_cast<const float4*>(p));
}

// GEMV over 4 pixel-pairs (8 px): acc[pp*4+i] += act[pp][in] * W[in*STRIDE+o4+i]
template <int NIN, int STRIDE>
__device__ __forceinline__ void mvN4(const float* __restrict__ W,
                                     const float* __restrict__ act, int o4, ull* acc) {
#pragma unroll 4
    for (int in = 0; in < NIN; ++in) {
        ulonglong2 A = ld16(act, in * 4), B = ld16(act, in * 4 + 2);
        float4 wv = ldg4(W + in * STRIDE + o4);
        ull w0 = dup2(wv.x), w1 = dup2(wv.y), w2 = dup2(wv.z), w3 = dup2(wv.w);
        acc[0]  = fma2(A.x, w0, acc[0]);  acc[1]  = fma2(A.x, w1, acc[1]);
        acc[2]  = fma2(A.x, w2, acc[2]);  acc[3]  = fma2(A.x, w3, acc[3]);
        acc[4]  = fma2(A.y, w0, acc[4]);  acc[5]  = fma2(A.y, w1, acc[5]);
        acc[6]  = fma2(A.y, w2, acc[6]);  acc[7]  = fma2(A.y, w3, acc[7]);
        acc[8]  = fma2(B.x, w0, acc[8]);  acc[9]  = fma2(B.x, w1, acc[9]);
        acc[10] = fma2(B.x, w2, acc[10]); acc[11] = fma2(B.x, w3, acc[11]);
        acc[12] = fma2(B.y, w0, acc[12]); acc[13] = fma2(B.y, w1, acc[13]);
        acc[14] = fma2(B.y, w2, acc[14]); acc[15] = fma2(B.y, w3, acc[15]);
    }
}

// GEMV over 2 down-col-pairs (4 distinct down pixels): acc[dp*4+i]
template <int NIN, int STRIDE>
__device__ __forceinline__ void mvN2(const float* __restrict__ W,
                                     const float* __restrict__ act, int o4, ull* acc) {
#pragma unroll 4
    for (int in = 0; in < NIN; ++in) {
        ulonglong2 A = ld16(act, in * 2);
        float4 wv = ldg4(W + in * STRIDE + o4);
        ull w0 = dup2(wv.x), w1 = dup2(wv.y), w2 = dup2(wv.z), w3 = dup2(wv.w);
        acc[0] = fma2(A.x, w0, acc[0]); acc[1] = fma2(A.x, w1, acc[1]);
        acc[2] = fma2(A.x, w2, acc[2]); acc[3] = fma2(A.x, w3, acc[3]);
        acc[4] = fma2(A.y, w0, acc[4]); acc[5] = fma2(A.y, w1, acc[5]);
        acc[6] = fma2(A.y, w2, acc[6]); acc[7] = fma2(A.y, w3, acc[7]);
    }
}

__device__ __forceinline__ void bias16(const float* bp, int o4, ull* acc) {
    float4 b = ldg4(bp + o4);
    ull b2[4] = {dup2(b.x), dup2(b.y), dup2(b.z), dup2(b.w)};
#pragma unroll
    for (int p = 0; p < 4; ++p)
#pragma unroll
        for (int i = 0; i < 4; ++i) acc[p * 4 + i] = b2[i];
}

__device__ __forceinline__ void softmax4(float s[4]) {
    float mx = fmaxf(fmaxf(s[0], s[1]), fmaxf(s[2], s[3]));
    float e0 = __expf(s[0] - mx), e1 = __expf(s[1] - mx);
    float e2 = __expf(s[2] - mx), e3 = __expf(s[3] - mx);
    float inv = 1.0f / (e0 + e1 + e2 + e3);
    s[0] = e0 * inv; s[1] = e1 * inv; s[2] = e2 * inv; s[3] = e3 * inv;
}

__global__ __launch_bounds__(64, 10)
void upsample_tf_kernel(
    const float* __restrict__ feat, const float* __restrict__ featup,
    const float* __restrict__ ctx_ln_b,
    const float* __restrict__ q_w, const float* __restrict__ q_b,
    const float* __restrict__ k_w, const float* __restrict__ k_b,
    const float* __restrict__ v_w, const float* __restrict__ v_b,
    const float* __restrict__ o_w, const float* __restrict__ o_b,
    const float* __restrict__ fc1_w, const float* __restrict__ fc1_b,
    const float* __restrict__ fc2_w, const float* __restrict__ fc2_b,
    const float* __restrict__ out1_b,
    const float* __restrict__ out2_w, const float* __restrict__ out2_b,
    const float* __restrict__ ctx_ln_g,
    float* __restrict__ out)
{
    __shared__ __align__(16) float s_sx[2][1024];  // 512 slots: normed x-side vec (4 pairs)
    __shared__ __align__(16) float s_cb[2][512];   // 256 slots: ctx row (2 dpairs)
    __shared__ __align__(16) float s_xr[2][1024];  // residual / fc1-hidden quarter
    __shared__ float s_sa[2][8][4];

    const int w = threadIdx.x >> 5, ln = threadIdx.x & 31, o4 = ln * 4;
    const int n0 = (blockIdx.x * 2 + w) * 8;
    if (n0 >= kN) return;
    const int b = n0 / kHWu;
    const int rr = n0 - b * kHWu;
    const int hu = rr / kWu, wu0 = rr - hu * kWu;
    const int w0c = wu0 >> 1;                       // multiple of 4

    float* sx = s_sx[w];
    float* cb = s_cb[w];
    float* xr = s_xr[w];
    float (*sa)[4] = s_sa[w];

    const int rh0 = min(hu >> 1, kHd - 1), rh1 = min((hu >> 1) + 1, kHd - 1);
    const int hd = ln >> 3;
    const float slope = exp2f(-(float)(hd + 1) * 1.1462406251802891f);
    const float* fmb = feat + ((size_t)b * kC) * kHWd;

    // gather ctx row j: 4 distinct down-cols -> 2 dpairs, cv[dp*4+i]
    auto gather = [&](int j, ull cv[8]) {
        const int ky = j >> 1, kx = j & 1;
        const int rhv = ky ? rh1 : rh0;
#pragma unroll
        for (int i = 0; i < 4; ++i) {
            const float* cp = fmb + (size_t)(o4 + i) * kHWd + rhv * kWd;
            float4 q4 = ldg4(cp + w0c);
            float e = __ldg(cp + min(w0c + 4, kWd - 1));
            float d0, d1, d2, d3;
            if (kx == 0) { d0 = q4.x; d1 = q4.y; d2 = q4.z; d3 = q4.w; }
            else         { d0 = q4.y; d1 = q4.z; d2 = q4.w; d3 = e;    }
            cv[0 + i] = pk2(d0, d1);
            cv[4 + i] = pk2(d2, d3);
        }
    };
    // build LN'd ctx row into cb: LN(ctx,eps)*g + b
    auto build = [&](int j, float eps, const ull* gd, const ull* bd) {
        ull cv[8], t0[4], t1[4];
        gather(j, cv);
        ln2(cv + 0, eps, t0);
        ln2(cv + 4, eps, t1);
        __syncwarp();   // previous cb readers done
#pragma unroll
        for (int i = 0; i < 4; ++i)
            st16(cb, (o4 + i) * 2, fma2(t0[i], gd[i], bd[i]), fma2(t1[i], gd[i], bd[i]));
        __syncwarp();
    };

    // ---- x load (8 px) -> residual xr (lane-private slots)
    {
        const float* fu = featup + ((size_t)b * kC) * kHWu + (size_t)hu * kWu + wu0;
#pragma unroll
        for (int i = 0; i < 4; ++i) {
            float4 A = ldg4(fu + (size_t)(o4 + i) * kHWu);
            float4 B = ldg4(fu + (size_t)(o4 + i) * kHWu + 4);
            st16(xr, (o4 + i) * 4 + 0, pk2(A.x, A.y), pk2(A.z, A.w));
            st16(xr, (o4 + i) * 4 + 2, pk2(B.x, B.y), pk2(B.z, B.w));
        }
    }

    const ull oneD = dup2(1.0f), zeroD = dup2(0.0f);
    const ull idG[4] = {oneD, oneD, oneD, oneD};
    const ull idB[4] = {zeroD, zeroD, zeroD, zeroD};

#pragma unroll 1
    for (int l = 0; l < 2; ++l) {
        const float* qW  = q_w  + l * 16384;
        const float* kW  = k_w  + l * 16384;
        const float* vW  = v_w  + l * 16384;
        const float* oW  = o_w  + l * 16384;
        const float* f1W = fc1_w + l * 65536;
        const float* f2W = fc2_w + l * 65536;

        ull gd[4], bd[4];
        {
            float4 gg = ldg4(ctx_ln_g + l * 128 + o4);
            float4 bb = ldg4(ctx_ln_b + l * 128 + o4);
            gd[0] = dup2(gg.x); gd[1] = dup2(gg.y); gd[2] = dup2(gg.z); gd[3] = dup2(gg.w);
            bd[0] = dup2(bb.x); bd[1] = dup2(bb.y); bd[2] = dup2(bb.z); bd[3] = dup2(bb.w);
        }

        // xn = LN(x) -> sx
        __syncwarp();
#pragma unroll
        for (int pp = 0; pp < 4; ++pp) {
            ull v4[4], t4[4];
#pragma unroll
            for (int i = 0; i < 4; ++i) v4[i] = ldp(xr, (o4 + i) * 4 + pp);
            ln2(v4, 1e-6f, t4);
#pragma unroll
            for (int i = 0; i < 4; ++i) stp(sx, (o4 + i) * 4 + pp, t4[i]);
        }
        __syncwarp();

        // q
        ull qa[16];
        bias16(q_b + l * 128, o4, qa);
        mvN4<128, 128>(qW, sx, o4, qa);

        // k rows -> raw scores (pixel-paired)
        ull sc2[16];
        {
            float4 kbv = ldg4(k_b + l * 128 + o4);
#pragma unroll 1
            for (int j = 0; j < 4; ++j) {
                build(j, 1e-5f, gd, bd);
                ull ka[8];
                ka[0] = ka[4] = dup2(kbv.x); ka[1] = ka[5] = dup2(kbv.y);
                ka[2] = ka[6] = dup2(kbv.z); ka[3] = ka[7] = dup2(kbv.w);
                mvN2<128, 128>(kW, cb, o4, ka);
                float kf[4][4];
#pragma unroll
                for (int dp = 0; dp < 2; ++dp)
#pragma unroll
                    for (int i = 0; i < 4; ++i) up2(ka[dp * 4 + i], kf[2 * dp][i], kf[2 * dp + 1][i]);
#pragma unroll
                for (int pp = 0; pp < 4; ++pp) {
                    ull s = mul2(qa[pp * 4 + 0], dup2(kf[pp][0]));
                    s = fma2(qa[pp * 4 + 1], dup2(kf[pp][1]), s);
                    s = fma2(qa[pp * 4 + 2], dup2(kf[pp][2]), s);
                    s = fma2(qa[pp * 4 + 3], dup2(kf[pp][3]), s);
                    s = add2(s, __shfl_xor_sync(0xffffffffu, s, 1));
                    s = add2(s, __shfl_xor_sync(0xffffffffu, s, 2));
                    s = add2(s, __shfl_xor_sync(0xffffffffu, s, 4));
                    sc2[j * 4 + pp] = s;
                }
            }
        }

        // softmax + ALiBi per pixel
        ull a2[16];
#pragma unroll
        for (int pp = 0; pp < 4; ++pp) {
            float sA[4], sB[4];
#pragma unroll
            for (int j = 0; j < 4; ++j) {
                float pa, pb; up2(sc2[j * 4 + pp], pa, pb);
                const int ky = j >> 1, kx = j & 1;
                const int rhv = ky ? rh1 : rh0;
                int rwv = min(w0c + pp + kx, kWd - 1);
                float dyv = -(float)abs(hu - 2 * rhv);
                int wupA = wu0 + 2 * pp;
                float cdA = dyv - (float)abs(wupA - 2 * rwv);
                float cdB = dyv - (float)abs(wupA + 1 - 2 * rwv);
                sA[j] = pa * 0.17677669529663687f + slope * cdA;
                sB[j] = pb * 0.17677669529663687f + slope * cdB;
            }
            softmax4(sA); softmax4(sB);
#pragma unroll
            for (int j = 0; j < 4; ++j) a2[j * 4 + pp] = pk2(sA[j], sB[j]);
        }

        // v rows -> ov
        ull ov[16];
#pragma unroll
        for (int t = 0; t < 16; ++t) ov[t] = zeroD;
        {
            float4 vbv = ldg4(v_b + l * 128 + o4);
#pragma unroll 1
            for (int j = 0; j < 4; ++j) {
                build(j, 1e-5f, gd, bd);
                ull va[8];
                va[0] = va[4] = dup2(vbv.x); va[1] = va[5] = dup2(vbv.y);
                va[2] = va[6] = dup2(vbv.z); va[3] = va[7] = dup2(vbv.w);
                mvN2<128, 128>(vW, cb, o4, va);
                float vf[4][4];
#pragma unroll
                for (int dp = 0; dp < 2; ++dp)
#pragma unroll
                    for (int i = 0; i < 4; ++i) up2(va[dp * 4 + i], vf[2 * dp][i], vf[2 * dp + 1][i]);
#pragma unroll
                for (int pp = 0; pp < 4; ++pp)
#pragma unroll
                    for (int i = 0; i < 4; ++i)
                        ov[pp * 4 + i] = fma2(a2[j * 4 + pp], dup2(vf[pp][i]), ov[pp * 4 + i]);
            }
        }

        // ov -> sx
        __syncwarp();
#pragma unroll
        for (int i = 0; i < 4; ++i) {
            st16(sx, (o4 + i) * 4 + 0, ov[0 * 4 + i], ov[1 * 4 + i]);
            st16(sx, (o4 + i) * 4 + 2, ov[2 * 4 + i], ov[3 * 4 + i]);
        }
        __syncwarp();

        // o-proj; x += ; hn = LN(x) -> sx
        {
            ull oa[16];
            bias16(o_b + l * 128, o4, oa);
            mvN4<128, 128>(oW, sx, o4, oa);
            __syncwarp();   // o-proj reads of sx done
#pragma unroll
            for (int pp = 0; pp < 4; ++pp) {
                ull v4[4], t4[4];
#pragma unroll
                for (int i = 0; i < 4; ++i) {
                    v4[i] = add2(ldp(xr, (o4 + i) * 4 + pp), oa[pp * 4 + i]);
                    stp(xr, (o4 + i) * 4 + pp, v4[i]);
                }
                ln2(v4, 1e-6f, t4);
#pragma unroll
                for (int i = 0; i < 4; ++i) stp(sx, (o4 + i) * 4 + pp, t4[i]);
            }
            __syncwarp();
        }

        // MLP: fa starts at residual + fc2 bias; xr reused as hidden quarter
        {
            ull fa[16];
            {
                float4 fb = ldg4(fc2_b + l * 128 + o4);
                ull b2[4] = {dup2(fb.x), dup2(fb.y), dup2(fb.z), dup2(fb.w)};
#pragma unroll
                for (int pp = 0; pp < 4; ++pp)
#pragma unroll
                    for (int i = 0; i < 4; ++i)
                        fa[pp * 4 + i] = add2(ldp(xr, (o4 + i) * 4 + pp), b2[i]);
            }
#pragma unroll 1
            for (int qtr = 0; qtr < 4; ++qtr) {
                ull f1[16];
                bias16(fc1_b + l * 512 + qtr * 128, o4, f1);
                mvN4<128, 512>(f1W + qtr * 128, sx, o4, f1);
                __syncwarp();   // fc2 readers of xr (prev qtr) done
#pragma unroll
                for (int i = 0; i < 4; ++i) {
                    st16(xr, (o4 + i) * 4 + 0, gelu_t2(f1[0 * 4 + i]), gelu_t2(f1[1 * 4 + i]));
                    st16(xr, (o4 + i) * 4 + 2, gelu_t2(f1[2 * 4 + i]), gelu_t2(f1[3 * 4 + i]));
                }
                __syncwarp();
                mvN4<128, 128>(f2W + qtr * 16384, xr, o4, fa);
            }
            __syncwarp();   // last fc2 readers done
#pragma unroll
            for (int i = 0; i < 4; ++i) {
                st16(xr, (o4 + i) * 4 + 0, fa[0 * 4 + i], fa[1 * 4 + i]);
                st16(xr, (o4 + i) * 4 + 2, fa[2 * 4 + i], fa[3 * 4 + i]);
            }
        }
    }

    // ---- final head
    {
        // xf = LN(x) -> sx
        __syncwarp();
#pragma unroll
        for (int pp = 0; pp < 4; ++pp) {
            ull v4[4], t4[4];
#pragma unroll
            for (int i = 0; i < 4; ++i) v4[i] = ldp(xr, (o4 + i) * 4 + pp);
            ln2(v4, 1e-6f, t4);
#pragma unroll
            for (int i = 0; i < 4; ++i) stp(sx, (o4 + i) * 4 + pp, t4[i]);
        }
        __syncwarp();

        ull s2[16];
#pragma unroll
        for (int t = 0; t < 16; ++t) s2[t] = zeroD;

#pragma unroll 1
        for (int r = 0; r < 3; ++r) {
            ull tb[16];
            bias16(out1_b + r * 128, o4, tb);
            mvN4<128, 384>(g_WA + r * 128, sx, o4, tb);
            float4 w2v = ldg4(out2_w + r * 128 + o4);
            ull wd4[4] = {dup2(w2v.x), dup2(w2v.y), dup2(w2v.z), dup2(w2v.w)};
#pragma unroll 1
            for (int j = 0; j < 4; ++j) {
                build(j, 1e-6f, idG, idB);
                ull us[8];
#pragma unroll
                for (int t = 0; t < 8; ++t) us[t] = zeroD;
                mvN2<128, 384>(g_WB + r * 128, cb, o4, us);
                float uf[4][4];
#pragma unroll
                for (int dp = 0; dp < 2; ++dp)
#pragma unroll
                    for (int i = 0; i < 4; ++i) up2(us[dp * 4 + i], uf[2 * dp][i], uf[2 * dp + 1][i]);
#pragma unroll
                for (int pp = 0; pp < 4; ++pp)
#pragma unroll
                    for (int i = 0; i < 4; ++i)
                        s2[j * 4 + pp] = fma2(gelu_e2(add2(tb[pp * 4 + i], dup2(uf[pp][i]))),
                                              wd4[i], s2[j * 4 + pp]);
            }
        }

        const float o2b = __ldg(out2_b);
#pragma unroll
        for (int pp = 0; pp < 4; ++pp)
#pragma unroll
            for (int j = 0; j < 4; ++j) {
                ull t = wsum2(s2[j * 4 + pp]);
                if (ln == 0) {
                    float a, bv; up2(t, a, bv);
                    sa[2 * pp][j] = a + o2b;
                    sa[2 * pp + 1][j] = bv + o2b;
                }
            }
        __syncwarp();

        {
            int px = ln >> 2, j = ln & 3;
            float l0 = sa[px][0], l1 = sa[px][1], l2 = sa[px][2], l3 = sa[px][3];
            float mx = fmaxf(fmaxf(l0, l1), fmaxf(l2, l3));
            float den = __expf(l0 - mx) + __expf(l1 - mx) + __expf(l2 - mx) + __expf(l3 - mx);
            float e = __expf(sa[px][j] - mx);
            out[(((size_t)b * 4 + j) * kHu + hu) * kWu + wu0 + px] = e / den;
        }
    }
}

extern "C" void kernel_launch(void* const* d_in, const int* in_sizes, int n_in,
                              void* d_out, int out_size) {
    const float* feat     = (const float*)d_in[0];
    const float* featup   = (const float*)d_in[1];
    const float* ctx_ln_b = (const float*)d_in[2];
    const float* q_w      = (const float*)d_in[3];
    const float* q_b      = (const float*)d_in[4];
    const float* k_w      = (const float*)d_in[5];
    const float* k_b      = (const float*)d_in[6];
    const float* v_w      = (const float*)d_in[7];
    const float* v_b      = (const float*)d_in[8];
    const float* o_w      = (const float*)d_in[9];
    const float* o_b      = (const float*)d_in[10];
    const float* fc1_w    = (const float*)d_in[11];
    const float* fc1_b    = (const float*)d_in[12];
    const float* fc2_w    = (const float*)d_in[13];
    const float* fc2_b    = (const float*)d_in[14];
    const float* out1_w   = (const float*)d_in[15];
    const float* out1_b   = (const float*)d_in[16];
    const float* out2_w   = (const float*)d_in[17];
    const float* out2_b   = (const float*)d_in[18];
    const float* ctx_ln_g = (const float*)d_in[19];

    prep_kernel<<<(128 * 384 + 255) / 256, 256>>>(out1_w);
    upsample_tf_kernel<<<kN / 16, 64>>>(
        feat, featup, ctx_ln_b, q_w, q_b, k_w, k_b, v_w, v_b, o_w, o_b,
        fc1_w, fc1_b, fc2_w, fc2_b, out1_b, out2_w, out2_b, ctx_ln_g,
        (float*)d_out);
}

// round 13
// speedup vs baseline: 1.2474x; 1.2474x over previous
#include <cuda_runtime.h>
#include <math.h>

typedef unsigned long long ull;

namespace {
constexpr int kB = 2, kC = 128, kHd = 64, kWd = 96, kHu = 128, kWu = 192;
constexpr int kN = kB * kHu * kWu;
constexpr int kHWd = kHd * kWd, kHWu = kHu * kWu;
}

__device__ float g_WA[128 * 384];
__device__ float g_WB[128 * 384];

__global__ void prep_kernel(const float* __restrict__ o1w) {
    int i = blockIdx.x * blockDim.x + threadIdx.x;
    if (i < 128 * 384) {
        int in = i / 384, o = i - in * 384;
        float w2 = o1w[(256 + in) * 384 + o];
        g_WA[i] = o1w[in * 384 + o] + w2;
        g_WB[i] = o1w[(128 + in) * 384 + o] - w2;
    }
}

// ---- packed f32x2 (SASS FFMA2, PTX-only) ----
__device__ __forceinline__ ull pk2(float a, float b) {
    ull r; asm("mov.b64 %0,{%1,%2};" : "=l"(r) : "f"(a), "f"(b)); return r;
}
__device__ __forceinline__ ull dup2(float a) { return pk2(a, a); }
__device__ __forceinline__ void up2(ull v, float& a, float& b) {
    asm("mov.b64 {%0,%1},%2;" : "=f"(a), "=f"(b) : "l"(v));
}
__device__ __forceinline__ ull fma2(ull a, ull b, ull c) {
    ull d; asm("fma.rn.f32x2 %0,%1,%2,%3;" : "=l"(d) : "l"(a), "l"(b), "l"(c)); return d;
}
__device__ __forceinline__ ull add2(ull a, ull b) {
    ull d; asm("add.rn.f32x2 %0,%1,%2;" : "=l"(d) : "l"(a), "l"(b)); return d;
}
__device__ __forceinline__ ull mul2(ull a, ull b) {
    ull d; asm("mul.rn.f32x2 %0,%1,%2;" : "=l"(d) : "l"(a), "l"(b)); return d;
}

// 8B-slot smem, XOR swizzle on bits [1:4) (bit0 kept -> 16B pairs stay intact)
__device__ __forceinline__ int swz(int s) { return s ^ ((s >> 4) & 14); }
__device__ __forceinline__ ull ldp(const float* b, int s) {
    return *reinterpret_cast<const ull*>(b + 2 * swz(s));
}
__device__ __forceinline__ void stp(float* b, int s, ull v) {
    *reinterpret_cast<ull*>(b + 2 * swz(s)) = v;
}
__device__ __forceinline__ ulonglong2 ld16(const float* b, int s) {  // s even
    return *reinterpret_cast<const ulonglong2*>(b + 2 * swz(s));
}
__device__ __forceinline__ void st16(float* b, int s, ull x, ull y) {  // s even
    *reinterpret_cast<ulonglong2*>(b + 2 * swz(s)) = make_ulonglong2(x, y);
}

__device__ __forceinline__ ull wsum2(ull v) {
#pragma unroll
    for (int o = 16; o; o >>= 1) v = add2(v, __shfl_xor_sync(0xffffffffu, v, o));
    return v;
}

// LN of 2 independent 128-ch vectors packed as a pair: v[i] = ch (o4+i)
__device__ __forceinline__ void ln2(const ull v[4], float eps, ull o[4]) {
    ull s = add2(add2(v[0], v[1]), add2(v[2], v[3]));
    ull q = fma2(v[0], v[0], fma2(v[1], v[1], fma2(v[2], v[2], mul2(v[3], v[3]))));
    s = wsum2(s); q = wsum2(q);
    float s0, s1, q0, q1; up2(s, s0, s1); up2(q, q0, q1);
    float m0 = s0 * (1.0f / 128.0f), m1 = s1 * (1.0f / 128.0f);
    float r0 = rsqrtf(fmaxf(q0 * (1.0f / 128.0f) - m0 * m0, 0.0f) + eps);
    float r1 = rsqrtf(fmaxf(q1 * (1.0f / 128.0f) - m1 * m1, 0.0f) + eps);
    ull nm = pk2(-m0, -m1), rr = pk2(r0, r1);
#pragma unroll
    for (int i = 0; i < 4; ++i) o[i] = mul2(add2(v[i], nm), rr);
}

// fast tanh-gelu: x * sigmoid(2u), u = 0.79788456(x + 0.044715 x^3)
__device__ __forceinline__ float gelu_t(float x) {
    float x2 = x * x;
    float arg = -1.5957691216057308f * fmaf(0.044715f * x2, x, x);
    return __fdividef(x, 1.0f + __expf(arg));
}
__device__ __forceinline__ ull gelu_t2(ull v) { float a, b; up2(v, a, b); return pk2(gelu_t(a), gelu_t(b)); }
__device__ __forceinline__ float gelu_e(float x) { return 0.5f * x * (1.0f + erff(x * 0.7071067811865475f)); }
__device__ __forceinline__ ull gelu_e2(ull v) { float a, b; up2(v, a, b); return pk2(gelu_e(a), gelu_e(b)); }

__device__ __forceinline__ float4 ldg4(const float* p) {
    return __ldg(reinterpret_cast<const float4*>(p));
}

// GEMV over 4 pixel-pairs (8 px): acc[pp*4+i] += act[pp][in] * W[in*STRIDE+o4+i]
template <int NIN, int STRIDE>
__device__ __forceinline__ void mvN4(const float* __restrict__ W,
                                     const float* __restrict__ act, int o4, ull* acc) {
#pragma unroll 4
    for (int in = 0; in < NIN; ++in) {
        ulonglong2 A = ld16(act, in * 4), B = ld16(act, in * 4 + 2);
        float4 wv = ldg4(W + in * STRIDE + o4);
        ull w0 = dup2(wv.x), w1 = dup2(wv.y), w2 = dup2(wv.z), w3 = dup2(wv.w);
        acc[0]  = fma2(A.x, w0, acc[0]);  acc[1]  = fma2(A.x, w1, acc[1]);
        acc[2]  = fma2(A.x, w2, acc[2]);  acc[3]  = fma2(A.x, w3, acc[3]);
        acc[4]  = fma2(A.y, w0, acc[4]);  acc[5]  = fma2(A.y, w1, acc[5]);
        acc[6]  = fma2(A.y, w2, acc[6]);  acc[7]  = fma2(A.y, w3, acc[7]);
        acc[8]  = fma2(B.x, w0, acc[8]);  acc[9]  = fma2(B.x, w1, acc[9]);
        acc[10] = fma2(B.x, w2, acc[10]); acc[11] = fma2(B.x, w3, acc[11]);
        acc[12] = fma2(B.y, w0, acc[12]); acc[13] = fma2(B.y, w1, acc[13]);
        acc[14] = fma2(B.y, w2, acc[14]); acc[15] = fma2(B.y, w3, acc[15]);
    }
}

// GEMV over 2 down-col-pairs (4 distinct down pixels): acc[dp*4+i]
template <int NIN, int STRIDE>
__device__ __forceinline__ void mvN2(const float* __restrict__ W,
                                     const float* __restrict__ act, int o4, ull* acc) {
#pragma unroll 4
    for (int in = 0; in < NIN; ++in) {
        ulonglong2 A = ld16(act, in * 2);
        float4 wv = ldg4(W + in * STRIDE + o4);
        ull w0 = dup2(wv.x), w1 = dup2(wv.y), w2 = dup2(wv.z), w3 = dup2(wv.w);
        acc[0] = fma2(A.x, w0, acc[0]); acc[1] = fma2(A.x, w1, acc[1]);
        acc[2] = fma2(A.x, w2, acc[2]); acc[3] = fma2(A.x, w3, acc[3]);
        acc[4] = fma2(A.y, w0, acc[4]); acc[5] = fma2(A.y, w1, acc[5]);
        acc[6] = fma2(A.y, w2, acc[6]); acc[7] = fma2(A.y, w3, acc[7]);
    }
}

__device__ __forceinline__ void bias16(const float* bp, int o4, ull* acc) {
    float4 b = ldg4(bp + o4);
    ull b2[4] = {dup2(b.x), dup2(b.y), dup2(b.z), dup2(b.w)};
#pragma unroll
    for (int p = 0; p < 4; ++p)
#pragma unroll
        for (int i = 0; i < 4; ++i) acc[p * 4 + i] = b2[i];
}

__device__ __forceinline__ void softmax4(float s[4]) {
    float mx = fmaxf(fmaxf(s[0], s[1]), fmaxf(s[2], s[3]));
    float e0 = __expf(s[0] - mx), e1 = __expf(s[1] - mx);
    float e2 = __expf(s[2] - mx), e3 = __expf(s[3] - mx);
    float inv = 1.0f / (e0 + e1 + e2 + e3);
    s[0] = e0 * inv; s[1] = e1 * inv; s[2] = e2 * inv; s[3] = e3 * inv;
}

__global__ __launch_bounds__(64, 8)
void upsample_tf_kernel(
    const float* __restrict__ feat, const float* __restrict__ featup,
    const float* __restrict__ ctx_ln_b,
    const float* __restrict__ q_w, const float* __restrict__ q_b,
    const float* __restrict__ k_w, const float* __restrict__ k_b,
    const float* __restrict__ v_w, const float* __restrict__ v_b,
    const float* __restrict__ o_w, const float* __restrict__ o_b,
    const float* __restrict__ fc1_w, const float* __restrict__ fc1_b,
    const float* __restrict__ fc2_w, const float* __restrict__ fc2_b,
    const float* __restrict__ out1_b,
    const float* __restrict__ out2_w, const float* __restrict__ out2_b,
    const float* __restrict__ ctx_ln_g,
    float* __restrict__ out)
{
    __shared__ __align__(16) float s_sx[2][1024];  // 512 slots: normed x-side vec (4 pairs)
    __shared__ __align__(16) float s_cb[2][512];   // 256 slots: ctx row (2 dpairs)
    __shared__ __align__(16) float s_xr[2][1024];  // residual / fc1-hidden quarter
    __shared__ float s_sa[2][8][4];

    const int w = threadIdx.x >> 5, ln = threadIdx.x & 31, o4 = ln * 4;
    const int n0 = (blockIdx.x * 2 + w) * 8;
    if (n0 >= kN) return;
    const int b = n0 / kHWu;
    const int rr = n0 - b * kHWu;
    const int hu = rr / kWu, wu0 = rr - hu * kWu;
    const int w0c = wu0 >> 1;                       // multiple of 4

    float* sx = s_sx[w];
    float* cb = s_cb[w];
    float* xr = s_xr[w];
    float (*sa)[4] = s_sa[w];

    const int rh0 = min(hu >> 1, kHd - 1), rh1 = min((hu >> 1) + 1, kHd - 1);
    const int hd = ln >> 3;
    const float slope = exp2f(-(float)(hd + 1) * 1.1462406251802891f);
    const float* fmb = feat + ((size_t)b * kC) * kHWd;

    // gather ctx row j: 4 distinct down-cols -> 2 dpairs, cv[dp*4+i]
    auto gather = [&](int j, ull cv[8]) {
        const int ky = j >> 1, kx = j & 1;
        const int rhv = ky ? rh1 : rh0;
#pragma unroll
        for (int i = 0; i < 4; ++i) {
            const float* cp = fmb + (size_t)(o4 + i) * kHWd + rhv * kWd;
            float4 q4 = ldg4(cp + w0c);
            float e = __ldg(cp + min(w0c + 4, kWd - 1));
            float d0, d1, d2, d3;
            if (kx == 0) { d0 = q4.x; d1 = q4.y; d2 = q4.z; d3 = q4.w; }
            else         { d0 = q4.y; d1 = q4.z; d2 = q4.w; d3 = e;    }
            cv[0 + i] = pk2(d0, d1);
            cv[4 + i] = pk2(d2, d3);
        }
    };
    // build LN'd ctx row into cb: LN(ctx,eps)*g + b
    auto build = [&](int j, float eps, const ull* gd, const ull* bd) {
        ull cv[8], t0[4], t1[4];
        gather(j, cv);
        ln2(cv + 0, eps, t0);
        ln2(cv + 4, eps, t1);
        __syncwarp();   // previous cb readers done
#pragma unroll
        for (int i = 0; i < 4; ++i)
            st16(cb, (o4 + i) * 2, fma2(t0[i], gd[i], bd[i]), fma2(t1[i], gd[i], bd[i]));
        __syncwarp();
    };

    // ---- x load (8 px) -> residual xr (lane-private slots)
    {
        const float* fu = featup + ((size_t)b * kC) * kHWu + (size_t)hu * kWu + wu0;
#pragma unroll
        for (int i = 0; i < 4; ++i) {
            float4 A = ldg4(fu + (size_t)(o4 + i) * kHWu);
            float4 B = ldg4(fu + (size_t)(o4 + i) * kHWu + 4);
            st16(xr, (o4 + i) * 4 + 0, pk2(A.x, A.y), pk2(A.z, A.w));
            st16(xr, (o4 + i) * 4 + 2, pk2(B.x, B.y), pk2(B.z, B.w));
        }
    }

    const ull oneD = dup2(1.0f), zeroD = dup2(0.0f);
    const ull idG[4] = {oneD, oneD, oneD, oneD};
    const ull idB[4] = {zeroD, zeroD, zeroD, zeroD};

#pragma unroll 1
    for (int l = 0; l < 2; ++l) {
        const float* qW  = q_w  + l * 16384;
        const float* kW  = k_w  + l * 16384;
        const float* vW  = v_w  + l * 16384;
        const float* oW  = o_w  + l * 16384;
        const float* f1W = fc1_w + l * 65536;
        const float* f2W = fc2_w + l * 65536;

        ull gd[4], bd[4];
        {
            float4 gg = ldg4(ctx_ln_g + l * 128 + o4);
            float4 bb = ldg4(ctx_ln_b + l * 128 + o4);
            gd[0] = dup2(gg.x); gd[1] = dup2(gg.y); gd[2] = dup2(gg.z); gd[3] = dup2(gg.w);
            bd[0] = dup2(bb.x); bd[1] = dup2(bb.y); bd[2] = dup2(bb.z); bd[3] = dup2(bb.w);
        }

        // xn = LN(x) -> sx
        __syncwarp();
#pragma unroll
        for (int pp = 0; pp < 4; ++pp) {
            ull v4[4], t4[4];
#pragma unroll
            for (int i = 0; i < 4; ++i) v4[i] = ldp(xr, (o4 + i) * 4 + pp);
            ln2(v4, 1e-6f, t4);
#pragma unroll
            for (int i = 0; i < 4; ++i) stp(sx, (o4 + i) * 4 + pp, t4[i]);
        }
        __syncwarp();

        // q
        ull qa[16];
        bias16(q_b + l * 128, o4, qa);
        mvN4<128, 128>(qW, sx, o4, qa);

        // k rows -> raw scores (pixel-paired)
        ull sc2[16];
        {
            float4 kbv = ldg4(k_b + l * 128 + o4);
#pragma unroll 1
            for (int j = 0; j < 4; ++j) {
                build(j, 1e-5f, gd, bd);
                ull ka[8];
                ka[0] = ka[4] = dup2(kbv.x); ka[1] = ka[5] = dup2(kbv.y);
                ka[2] = ka[6] = dup2(kbv.z); ka[3] = ka[7] = dup2(kbv.w);
                mvN2<128, 128>(kW, cb, o4, ka);
                float kf[4][4];
#pragma unroll
                for (int dp = 0; dp < 2; ++dp)
#pragma unroll
                    for (int i = 0; i < 4; ++i) up2(ka[dp * 4 + i], kf[2 * dp][i], kf[2 * dp + 1][i]);
#pragma unroll
                for (int pp = 0; pp < 4; ++pp) {
                    ull s = mul2(qa[pp * 4 + 0], dup2(kf[pp][0]));
                    s = fma2(qa[pp * 4 + 1], dup2(kf[pp][1]), s);
                    s = fma2(qa[pp * 4 + 2], dup2(kf[pp][2]), s);
                    s = fma2(qa[pp * 4 + 3], dup2(kf[pp][3]), s);
                    s = add2(s, __shfl_xor_sync(0xffffffffu, s, 1));
                    s = add2(s, __shfl_xor_sync(0xffffffffu, s, 2));
                    s = add2(s, __shfl_xor_sync(0xffffffffu, s, 4));
                    sc2[j * 4 + pp] = s;
                }
            }
        }

        // softmax + ALiBi per pixel
        ull a2[16];
#pragma unroll
        for (int pp = 0; pp < 4; ++pp) {
            float sA[4], sB[4];
#pragma unroll
            for (int j = 0; j < 4; ++j) {
                float pa, pb; up2(sc2[j * 4 + pp], pa, pb);
                const int ky = j >> 1, kx = j & 1;
                const int rhv = ky ? rh1 : rh0;
                int rwv = min(w0c + pp + kx, kWd - 1);
                float dyv = -(float)abs(hu - 2 * rhv);
                int wupA = wu0 + 2 * pp;
                float cdA = dyv - (float)abs(wupA - 2 * rwv);
                float cdB = dyv - (float)abs(wupA + 1 - 2 * rwv);
                sA[j] = pa * 0.17677669529663687f + slope * cdA;
                sB[j] = pb * 0.17677669529663687f + slope * cdB;
            }
            softmax4(sA); softmax4(sB);
#pragma unroll
            for (int j = 0; j < 4; ++j) a2[j * 4 + pp] = pk2(sA[j], sB[j]);
        }

        // v rows -> ov
        ull ov[16];
#pragma unroll
        for (int t = 0; t < 16; ++t) ov[t] = zeroD;
        {
            float4 vbv = ldg4(v_b + l * 128 + o4);
#pragma unroll 1
            for (int j = 0; j < 4; ++j) {
                build(j, 1e-5f, gd, bd);
                ull va[8];
                va[0] = va[4] = dup2(vbv.x); va[1] = va[5] = dup2(vbv.y);
                va[2] = va[6] = dup2(vbv.z); va[3] = va[7] = dup2(vbv.w);
                mvN2<128, 128>(vW, cb, o4, va);
                float vf[4][4];
#pragma unroll
                for (int dp = 0; dp < 2; ++dp)
#pragma unroll
                    for (int i = 0; i < 4; ++i) up2(va[dp * 4 + i], vf[2 * dp][i], vf[2 * dp + 1][i]);
#pragma unroll
                for (int pp = 0; pp < 4; ++pp)
#pragma unroll
                    for (int i = 0; i < 4; ++i)
                        ov[pp * 4 + i] = fma2(a2[j * 4 + pp], dup2(vf[pp][i]), ov[pp * 4 + i]);
            }
        }

        // ov -> sx
        __syncwarp();
#pragma unroll
        for (int i = 0; i < 4; ++i) {
            st16(sx, (o4 + i) * 4 + 0, ov[0 * 4 + i], ov[1 * 4 + i]);
            st16(sx, (o4 + i) * 4 + 2, ov[2 * 4 + i], ov[3 * 4 + i]);
        }
        __syncwarp();

        // o-proj; x += ; hn = LN(x) -> sx
        {
            ull oa[16];
            bias16(o_b + l * 128, o4, oa);
            mvN4<128, 128>(oW, sx, o4, oa);
            __syncwarp();   // o-proj reads of sx done
#pragma unroll
            for (int pp = 0; pp < 4; ++pp) {
                ull v4[4], t4[4];
#pragma unroll
                for (int i = 0; i < 4; ++i) {
                    v4[i] = add2(ldp(xr, (o4 + i) * 4 + pp), oa[pp * 4 + i]);
                    stp(xr, (o4 + i) * 4 + pp, v4[i]);
                }
                ln2(v4, 1e-6f, t4);
#pragma unroll
                for (int i = 0; i < 4; ++i) stp(sx, (o4 + i) * 4 + pp, t4[i]);
            }
            __syncwarp();
        }

        // MLP: fa starts at residual + fc2 bias; xr reused as hidden quarter
        {
            ull fa[16];
            {
                float4 fb = ldg4(fc2_b + l * 128 + o4);
                ull b2[4] = {dup2(fb.x), dup2(fb.y), dup2(fb.z), dup2(fb.w)};
#pragma unroll
                for (int pp = 0; pp < 4; ++pp)
#pragma unroll
                    for (int i = 0; i < 4; ++i)
                        fa[pp * 4 + i] = add2(ldp(xr, (o4 + i) * 4 + pp), b2[i]);
            }
#pragma unroll 1
            for (int qtr = 0; qtr < 4; ++qtr) {
                ull f1[16];
                bias16(fc1_b + l * 512 + qtr * 128, o4, f1);
                mvN4<128, 512>(f1W + qtr * 128, sx, o4, f1);
                __syncwarp();   // fc2 readers of xr (prev qtr) done
#pragma unroll
                for (int i = 0; i < 4; ++i) {
                    st16(xr, (o4 + i) * 4 + 0, gelu_t2(f1[0 * 4 + i]), gelu_t2(f1[1 * 4 + i]));
                    st16(xr, (o4 + i) * 4 + 2, gelu_t2(f1[2 * 4 + i]), gelu_t2(f1[3 * 4 + i]));
                }
                __syncwarp();
                mvN4<128, 128>(f2W + qtr * 16384, xr, o4, fa);
            }
            __syncwarp();   // last fc2 readers done
#pragma unroll
            for (int i = 0; i < 4; ++i) {
                st16(xr, (o4 + i) * 4 + 0, fa[0 * 4 + i], fa[1 * 4 + i]);
                st16(xr, (o4 + i) * 4 + 2, fa[2 * 4 + i], fa[3 * 4 + i]);
            }
        }
    }

    // ---- final head
    {
        // xf = LN(x) -> sx
        __syncwarp();
#pragma unroll
        for (int pp = 0; pp < 4; ++pp) {
            ull v4[4], t4[4];
#pragma unroll
            for (int i = 0; i < 4; ++i) v4[i] = ldp(xr, (o4 + i) * 4 + pp);
            ln2(v4, 1e-6f, t4);
#pragma unroll
            for (int i = 0; i < 4; ++i) stp(sx, (o4 + i) * 4 + pp, t4[i]);
        }
        __syncwarp();

        ull s2[16];
#pragma unroll
        for (int t = 0; t < 16; ++t) s2[t] = zeroD;

#pragma unroll 1
        for (int r = 0; r < 3; ++r) {
            ull tb[16];
            bias16(out1_b + r * 128, o4, tb);
            mvN4<128, 384>(g_WA + r * 128, sx, o4, tb);
            float4 w2v = ldg4(out2_w + r * 128 + o4);
            ull wd4[4] = {dup2(w2v.x), dup2(w2v.y), dup2(w2v.z), dup2(w2v.w)};
#pragma unroll 1
            for (int j = 0; j < 4; ++j) {
                build(j, 1e-6f, idG, idB);
                ull us[8];
#pragma unroll
                for (int t = 0; t < 8; ++t) us[t] = zeroD;
                mvN2<128, 384>(g_WB + r * 128, cb, o4, us);
                float uf[4][4];
#pragma unroll
                for (int dp = 0; dp < 2; ++dp)
#pragma unroll
                    for (int i = 0; i < 4; ++i) up2(us[dp * 4 + i], uf[2 * dp][i], uf[2 * dp + 1][i]);
#pragma unroll
                for (int pp = 0; pp < 4; ++pp)
#pragma unroll
                    for (int i = 0; i < 4; ++i)
                        s2[j * 4 + pp] = fma2(gelu_e2(add2(tb[pp * 4 + i], dup2(uf[pp][i]))),
                                              wd4[i], s2[j * 4 + pp]);
            }
        }

        const float o2b = __ldg(out2_b);
#pragma unroll
        for (int pp = 0; pp < 4; ++pp)
#pragma unroll
            for (int j = 0; j < 4; ++j) {
                ull t = wsum2(s2[j * 4 + pp]);
                if (ln == 0) {
                    float a, bv; up2(t, a, bv);
                    sa[2 * pp][j] = a + o2b;
                    sa[2 * pp + 1][j] = bv + o2b;
                }
            }
        __syncwarp();

        {
            int px = ln >> 2, j = ln & 3;
            float l0 = sa[px][0], l1 = sa[px][1], l2 = sa[px][2], l3 = sa[px][3];
            float mx = fmaxf(fmaxf(l0, l1), fmaxf(l2, l3));
            float den = __expf(l0 - mx) + __expf(l1 - mx) + __expf(l2 - mx) + __expf(l3 - mx);
            float e = __expf(sa[px][j] - mx);
            out[(((size_t)b * 4 + j) * kHu + hu) * kWu + wu0 + px] = e / den;
        }
    }
}

extern "C" void kernel_launch(void* const* d_in, const int* in_sizes, int n_in,
                              void* d_out, int out_size) {
    const float* feat     = (const float*)d_in[0];
    const float* featup   = (const float*)d_in[1];
    const float* ctx_ln_b = (const float*)d_in[2];
    const float* q_w      = (const float*)d_in[3];
    const float* q_b      = (const float*)d_in[4];
    const float* k_w      = (const float*)d_in[5];
    const float* k_b      = (const float*)d_in[6];
    const float* v_w      = (const float*)d_in[7];
    const float* v_b      = (const float*)d_in[8];
    const float* o_w      = (const float*)d_in[9];
    const float* o_b      = (const float*)d_in[10];
    const float* fc1_w    = (const float*)d_in[11];
    const float* fc1_b    = (const float*)d_in[12];
    const float* fc2_w    = (const float*)d_in[13];
    const float* fc2_b    = (const float*)d_in[14];
    const float* out1_w   = (const float*)d_in[15];
    const float* out1_b   = (const float*)d_in[16];
    const float* out2_w   = (const float*)d_in[17];
    const float* out2_b   = (const float*)d_in[18];
    const float* ctx_ln_g = (const float*)d_in[19];

    prep_kernel<<<(128 * 384 + 255) / 256, 256>>>(out1_w);
    upsample_tf_kernel<<<kN / 16, 64>>>(
        feat, featup, ctx_ln_b, q_w, q_b, k_w, k_b, v_w, v_b, o_w, o_b,
        fc1_w, fc1_b, fc2_w, fc2_b, out1_b, out2_w, out2_b, ctx_ln_g,
        (float*)d_out);
}

// round 14
// speedup vs baseline: 1.3343x; 1.0697x over previous
#include <cuda_runtime.h>
#include <math.h>

typedef unsigned long long ull;

namespace {
constexpr int kB = 2, kC = 128, kHd = 64, kWd = 96, kHu = 128, kWu = 192;
constexpr int kN = kB * kHu * kWu;
constexpr int kHWd = kHd * kWd, kHWu = kHu * kWu;
}

__device__ float g_WA[128 * 384];
__device__ float g_WB[128 * 384];

__global__ void prep_kernel(const float* __restrict__ o1w) {
    int i = blockIdx.x * blockDim.x + threadIdx.x;
    if (i < 128 * 384) {
        int in = i / 384, o = i - in * 384;
        float w2 = o1w[(256 + in) * 384 + o];
        g_WA[i] = o1w[in * 384 + o] + w2;
        g_WB[i] = o1w[(128 + in) * 384 + o] - w2;
    }
}

// ---- packed f32x2 (SASS FFMA2, PTX-only) ----
__device__ __forceinline__ ull pk2(float a, float b) {
    ull r; asm("mov.b64 %0,{%1,%2};" : "=l"(r) : "f"(a), "f"(b)); return r;
}
__device__ __forceinline__ ull dup2(float a) { return pk2(a, a); }
__device__ __forceinline__ void up2(ull v, float& a, float& b) {
    asm("mov.b64 {%0,%1},%2;" : "=f"(a), "=f"(b) : "l"(v));
}
__device__ __forceinline__ ull fma2(ull a, ull b, ull c) {
    ull d; asm("fma.rn.f32x2 %0,%1,%2,%3;" : "=l"(d) : "l"(a), "l"(b), "l"(c)); return d;
}
__device__ __forceinline__ ull add2(ull a, ull b) {
    ull d; asm("add.rn.f32x2 %0,%1,%2;" : "=l"(d) : "l"(a), "l"(b)); return d;
}
__device__ __forceinline__ ull mul2(ull a, ull b) {
    ull d; asm("mul.rn.f32x2 %0,%1,%2;" : "=l"(d) : "l"(a), "l"(b)); return d;
}

// 8B-slot smem, XOR swizzle on bits [1:4) (bit0 kept -> 16B pairs stay intact)
__device__ __forceinline__ int swz(int s) { return s ^ ((s >> 4) & 14); }
__device__ __forceinline__ ull ldp(const float* b, int s) {
    return *reinterpret_cast<const ull*>(b + 2 * swz(s));
}
__device__ __forceinline__ void stp(float* b, int s, ull v) {
    *reinterpret_cast<ull*>(b + 2 * swz(s)) = v;
}
__device__ __forceinline__ ulonglong2 ld16(const float* b, int s) {  // s even
    return *reinterpret_cast<const ulonglong2*>(b + 2 * swz(s));
}
__device__ __forceinline__ void st16(float* b, int s, ull x, ull y) {  // s even
    *reinterpret_cast<ulonglong2*>(b + 2 * swz(s)) = make_ulonglong2(x, y);
}

__device__ __forceinline__ ull wsum2(ull v) {
#pragma unroll
    for (int o = 16; o; o >>= 1) v = add2(v, __shfl_xor_sync(0xffffffffu, v, o));
    return v;
}

// LN of 2 independent 128-ch vectors packed as a pair: v[i] = ch (o4+i)
__device__ __forceinline__ void ln2(const ull v[4], float eps, ull o[4]) {
    ull s = add2(add2(v[0], v[1]), add2(v[2], v[3]));
    ull q = fma2(v[0], v[0], fma2(v[1], v[1], fma2(v[2], v[2], mul2(v[3], v[3]))));
    s = wsum2(s); q = wsum2(q);
    float s0, s1, q0, q1; up2(s, s0, s1); up2(q, q0, q1);
    float m0 = s0 * (1.0f / 128.0f), m1 = s1 * (1.0f / 128.0f);
    float r0 = rsqrtf(fmaxf(q0 * (1.0f / 128.0f) - m0 * m0, 0.0f) + eps);
    float r1 = rsqrtf(fmaxf(q1 * (1.0f / 128.0f) - m1 * m1, 0.0f) + eps);
    ull nm = pk2(-m0, -m1), rr = pk2(r0, r1);
#pragma unroll
    for (int i = 0; i < 4; ++i) o[i] = mul2(add2(v[i], nm), rr);
}

// fast tanh-gelu: x * sigmoid(2u), u = 0.79788456(x + 0.044715 x^3)
__device__ __forceinline__ float gelu_t(float x) {
    float x2 = x * x;
    float arg = -1.5957691216057308f * fmaf(0.044715f * x2, x, x);
    return __fdividef(x, 1.0f + __expf(arg));
}
__device__ __forceinline__ ull gelu_t2(ull v) { float a, b; up2(v, a, b); return pk2(gelu_t(a), gelu_t(b)); }
__device__ __forceinline__ float gelu_e(float x) { return 0.5f * x * (1.0f + erff(x * 0.7071067811865475f)); }
__device__ __forceinline__ ull gelu_e2(ull v) { float a, b; up2(v, a, b); return pk2(gelu_e(a), gelu_e(b)); }

__device__ __forceinline__ float4 ldg4(const float* p) {
    return __ldg(reinterpret_cast<const float4*>(p));
}

// GEMV over 4 pixel-pairs (8 px): acc[pp*4+i] += act[pp][in] * W[in*STRIDE+o4+i]
template <int NIN, int STRIDE>
__device__ __forceinline__ void mvN4(const float* __restrict__ W,
                                     const float* __restrict__ act, int o4, ull* acc) {
#pragma unroll 8
    for (int in = 0; in < NIN; ++in) {
        ulonglong2 A = ld16(act, in * 4), B = ld16(act, in * 4 + 2);
        float4 wv = ldg4(W + in * STRIDE + o4);
        ull w0 = dup2(wv.x), w1 = dup2(wv.y), w2 = dup2(wv.z), w3 = dup2(wv.w);
        acc[0]  = fma2(A.x, w0, acc[0]);  acc[1]  = fma2(A.x, w1, acc[1]);
        acc[2]  = fma2(A.x, w2, acc[2]);  acc[3]  = fma2(A.x, w3, acc[3]);
        acc[4]  = fma2(A.y, w0, acc[4]);  acc[5]  = fma2(A.y, w1, acc[5]);
        acc[6]  = fma2(A.y, w2, acc[6]);  acc[7]  = fma2(A.y, w3, acc[7]);
        acc[8]  = fma2(B.x, w0, acc[8]);  acc[9]  = fma2(B.x, w1, acc[9]);
        acc[10] = fma2(B.x, w2, acc[10]); acc[11] = fma2(B.x, w3, acc[11]);
        acc[12] = fma2(B.y, w0, acc[12]); acc[13] = fma2(B.y, w1, acc[13]);
        acc[14] = fma2(B.y, w2, acc[14]); acc[15] = fma2(B.y, w3, acc[15]);
    }
}

// GEMV over 2 down-col-pairs (4 distinct down pixels): acc[dp*4+i]
template <int NIN, int STRIDE>
__device__ __forceinline__ void mvN2(const float* __restrict__ W,
                                     const float* __restrict__ act, int o4, ull* acc) {
#pragma unroll 8
    for (int in = 0; in < NIN; ++in) {
        ulonglong2 A = ld16(act, in * 2);
        float4 wv = ldg4(W + in * STRIDE + o4);
        ull w0 = dup2(wv.x), w1 = dup2(wv.y), w2 = dup2(wv.z), w3 = dup2(wv.w);
        acc[0] = fma2(A.x, w0, acc[0]); acc[1] = fma2(A.x, w1, acc[1]);
        acc[2] = fma2(A.x, w2, acc[2]); acc[3] = fma2(A.x, w3, acc[3]);
        acc[4] = fma2(A.y, w0, acc[4]); acc[5] = fma2(A.y, w1, acc[5]);
        acc[6] = fma2(A.y, w2, acc[6]); acc[7] = fma2(A.y, w3, acc[7]);
    }
}

__device__ __forceinline__ void bias16(const float* bp, int o4, ull* acc) {
    float4 b = ldg4(bp + o4);
    ull b2[4] = {dup2(b.x), dup2(b.y), dup2(b.z), dup2(b.w)};
#pragma unroll
    for (int p = 0; p < 4; ++p)
#pragma unroll
        for (int i = 0; i < 4; ++i) acc[p * 4 + i] = b2[i];
}

__device__ __forceinline__ void softmax4(float s[4]) {
    float mx = fmaxf(fmaxf(s[0], s[1]), fmaxf(s[2], s[3]));
    float e0 = __expf(s[0] - mx), e1 = __expf(s[1] - mx);
    float e2 = __expf(s[2] - mx), e3 = __expf(s[3] - mx);
    float inv = 1.0f / (e0 + e1 + e2 + e3);
    s[0] = e0 * inv; s[1] = e1 * inv; s[2] = e2 * inv; s[3] = e3 * inv;
}

__global__ __launch_bounds__(64, 8)
void upsample_tf_kernel(
    const float* __restrict__ feat, const float* __restrict__ featup,
    const float* __restrict__ ctx_ln_b,
    const float* __restrict__ q_w, const float* __restrict__ q_b,
    const float* __restrict__ k_w, const float* __restrict__ k_b,
    const float* __restrict__ v_w, const float* __restrict__ v_b,
    const float* __restrict__ o_w, const float* __restrict__ o_b,
    const float* __restrict__ fc1_w, const float* __restrict__ fc1_b,
    const float* __restrict__ fc2_w, const float* __restrict__ fc2_b,
    const float* __restrict__ out1_b,
    const float* __restrict__ out2_w, const float* __restrict__ out2_b,
    const float* __restrict__ ctx_ln_g,
    float* __restrict__ out)
{
    __shared__ __align__(16) float s_sx[2][1024];  // 512 slots: normed x-side vec (4 pairs)
    __shared__ __align__(16) float s_cb[2][512];   // 256 slots: ctx row (2 dpairs)
    __shared__ __align__(16) float s_xr[2][1024];  // residual / fc1-hidden quarter
    __shared__ float s_sa[2][8][4];

    const int w = threadIdx.x >> 5, ln = threadIdx.x & 31, o4 = ln * 4;
    const int n0 = (blockIdx.x * 2 + w) * 8;
    if (n0 >= kN) return;
    const int b = n0 / kHWu;
    const int rr = n0 - b * kHWu;
    const int hu = rr / kWu, wu0 = rr - hu * kWu;
    const int w0c = wu0 >> 1;                       // multiple of 4

    float* sx = s_sx[w];
    float* cb = s_cb[w];
    float* xr = s_xr[w];
    float (*sa)[4] = s_sa[w];

    const int rh0 = min(hu >> 1, kHd - 1), rh1 = min((hu >> 1) + 1, kHd - 1);
    const int hd = ln >> 3;
    const float slope = exp2f(-(float)(hd + 1) * 1.1462406251802891f);
    const float* fmb = feat + ((size_t)b * kC) * kHWd;

    // gather ctx row j: 4 distinct down-cols -> 2 dpairs, cv[dp*4+i]
    auto gather = [&](int j, ull cv[8]) {
        const int ky = j >> 1, kx = j & 1;
        const int rhv = ky ? rh1 : rh0;
#pragma unroll
        for (int i = 0; i < 4; ++i) {
            const float* cp = fmb + (size_t)(o4 + i) * kHWd + rhv * kWd;
            float4 q4 = ldg4(cp + w0c);
            float e = __ldg(cp + min(w0c + 4, kWd - 1));
            float d0, d1, d2, d3;
            if (kx == 0) { d0 = q4.x; d1 = q4.y; d2 = q4.z; d3 = q4.w; }
            else         { d0 = q4.y; d1 = q4.z; d2 = q4.w; d3 = e;    }
            cv[0 + i] = pk2(d0, d1);
            cv[4 + i] = pk2(d2, d3);
        }
    };
    // build LN'd ctx row into cb: LN(ctx,eps)*g + b
    auto build = [&](int j, float eps, const ull* gd, const ull* bd) {
        ull cv[8], t0[4], t1[4];
        gather(j, cv);
        ln2(cv + 0, eps, t0);
        ln2(cv + 4, eps, t1);
        __syncwarp();   // previous cb readers done
#pragma unroll
        for (int i = 0; i < 4; ++i)
            st16(cb, (o4 + i) * 2, fma2(t0[i], gd[i], bd[i]), fma2(t1[i], gd[i], bd[i]));
        __syncwarp();
    };

    // ---- x load (8 px) -> residual xr (lane-private slots)
    {
        const float* fu = featup + ((size_t)b * kC) * kHWu + (size_t)hu * kWu + wu0;
#pragma unroll
        for (int i = 0; i < 4; ++i) {
            float4 A = ldg4(fu + (size_t)(o4 + i) * kHWu);
            float4 B = ldg4(fu + (size_t)(o4 + i) * kHWu + 4);
            st16(xr, (o4 + i) * 4 + 0, pk2(A.x, A.y), pk2(A.z, A.w));
            st16(xr, (o4 + i) * 4 + 2, pk2(B.x, B.y), pk2(B.z, B.w));
        }
    }

    const ull oneD = dup2(1.0f), zeroD = dup2(0.0f);
    const ull idG[4] = {oneD, oneD, oneD, oneD};
    const ull idB[4] = {zeroD, zeroD, zeroD, zeroD};

#pragma unroll 1
    for (int l = 0; l < 2; ++l) {
        const float* qW  = q_w  + l * 16384;
        const float* kW  = k_w  + l * 16384;
        const float* vW  = v_w  + l * 16384;
        const float* oW  = o_w  + l * 16384;
        const float* f1W = fc1_w + l * 65536;
        const float* f2W = fc2_w + l * 65536;

        ull gd[4], bd[4];
        {
            float4 gg = ldg4(ctx_ln_g + l * 128 + o4);
            float4 bb = ldg4(ctx_ln_b + l * 128 + o4);
            gd[0] = dup2(gg.x); gd[1] = dup2(gg.y); gd[2] = dup2(gg.z); gd[3] = dup2(gg.w);
            bd[0] = dup2(bb.x); bd[1] = dup2(bb.y); bd[2] = dup2(bb.z); bd[3] = dup2(bb.w);
        }

        // xn = LN(x) -> sx
        __syncwarp();
#pragma unroll
        for (int pp = 0; pp < 4; ++pp) {
            ull v4[4], t4[4];
#pragma unroll
            for (int i = 0; i < 4; ++i) v4[i] = ldp(xr, (o4 + i) * 4 + pp);
            ln2(v4, 1e-6f, t4);
#pragma unroll
            for (int i = 0; i < 4; ++i) stp(sx, (o4 + i) * 4 + pp, t4[i]);
        }
        __syncwarp();

        // q
        ull qa[16];
        bias16(q_b + l * 128, o4, qa);
        mvN4<128, 128>(qW, sx, o4, qa);

        // k rows -> raw scores (pixel-paired)
        ull sc2[16];
        {
            float4 kbv = ldg4(k_b + l * 128 + o4);
#pragma unroll 1
            for (int j = 0; j < 4; ++j) {
                build(j, 1e-5f, gd, bd);
                ull ka[8];
                ka[0] = ka[4] = dup2(kbv.x); ka[1] = ka[5] = dup2(kbv.y);
                ka[2] = ka[6] = dup2(kbv.z); ka[3] = ka[7] = dup2(kbv.w);
                mvN2<128, 128>(kW, cb, o4, ka);
                float kf[4][4];
#pragma unroll
                for (int dp = 0; dp < 2; ++dp)
#pragma unroll
                    for (int i = 0; i < 4; ++i) up2(ka[dp * 4 + i], kf[2 * dp][i], kf[2 * dp + 1][i]);
#pragma unroll
                for (int pp = 0; pp < 4; ++pp) {
                    ull s = mul2(qa[pp * 4 + 0], dup2(kf[pp][0]));
                    s = fma2(qa[pp * 4 + 1], dup2(kf[pp][1]), s);
                    s = fma2(qa[pp * 4 + 2], dup2(kf[pp][2]), s);
                    s = fma2(qa[pp * 4 + 3], dup2(kf[pp][3]), s);
                    s = add2(s, __shfl_xor_sync(0xffffffffu, s, 1));
                    s = add2(s, __shfl_xor_sync(0xffffffffu, s, 2));
                    s = add2(s, __shfl_xor_sync(0xffffffffu, s, 4));
                    sc2[j * 4 + pp] = s;
                }
            }
        }

        // softmax + ALiBi per pixel
        ull a2[16];
#pragma unroll
        for (int pp = 0; pp < 4; ++pp) {
            float sA[4], sB[4];
#pragma unroll
            for (int j = 0; j < 4; ++j) {
                float pa, pb; up2(sc2[j * 4 + pp], pa, pb);
                const int ky = j >> 1, kx = j & 1;
                const int rhv = ky ? rh1 : rh0;
                int rwv = min(w0c + pp + kx, kWd - 1);
                float dyv = -(float)abs(hu - 2 * rhv);
                int wupA = wu0 + 2 * pp;
                float cdA = dyv - (float)abs(wupA - 2 * rwv);
                float cdB = dyv - (float)abs(wupA + 1 - 2 * rwv);
                sA[j] = pa * 0.17677669529663687f + slope * cdA;
                sB[j] = pb * 0.17677669529663687f + slope * cdB;
            }
            softmax4(sA); softmax4(sB);
#pragma unroll
            for (int j = 0; j < 4; ++j) a2[j * 4 + pp] = pk2(sA[j], sB[j]);
        }

        // v rows -> ov
        ull ov[16];
#pragma unroll
        for (int t = 0; t < 16; ++t) ov[t] = zeroD;
        {
            float4 vbv = ldg4(v_b + l * 128 + o4);
#pragma unroll 1
            for (int j = 0; j < 4; ++j) {
                build(j, 1e-5f, gd, bd);
                ull va[8];
                va[0] = va[4] = dup2(vbv.x); va[1] = va[5] = dup2(vbv.y);
                va[2] = va[6] = dup2(vbv.z); va[3] = va[7] = dup2(vbv.w);
                mvN2<128, 128>(vW, cb, o4, va);
                float vf[4][4];
#pragma unroll
                for (int dp = 0; dp < 2; ++dp)
#pragma unroll
                    for (int i = 0; i < 4; ++i) up2(va[dp * 4 + i], vf[2 * dp][i], vf[2 * dp + 1][i]);
#pragma unroll
                for (int pp = 0; pp < 4; ++pp)
#pragma unroll
                    for (int i = 0; i < 4; ++i)
                        ov[pp * 4 + i] = fma2(a2[j * 4 + pp], dup2(vf[pp][i]), ov[pp * 4 + i]);
            }
        }

        // ov -> sx
        __syncwarp();
#pragma unroll
        for (int i = 0; i < 4; ++i) {
            st16(sx, (o4 + i) * 4 + 0, ov[0 * 4 + i], ov[1 * 4 + i]);
            st16(sx, (o4 + i) * 4 + 2, ov[2 * 4 + i], ov[3 * 4 + i]);
        }
        __syncwarp();

        // o-proj; x += ; hn = LN(x) -> sx
        {
            ull oa[16];
            bias16(o_b + l * 128, o4, oa);
            mvN4<128, 128>(oW, sx, o4, oa);
            __syncwarp();   // o-proj reads of sx done
#pragma unroll
            for (int pp = 0; pp < 4; ++pp) {
                ull v4[4], t4[4];
#pragma unroll
                for (int i = 0; i < 4; ++i) {
                    v4[i] = add2(ldp(xr, (o4 + i) * 4 + pp), oa[pp * 4 + i]);
                    stp(xr, (o4 + i) * 4 + pp, v4[i]);
                }
                ln2(v4, 1e-6f, t4);
#pragma unroll
                for (int i = 0; i < 4; ++i) stp(sx, (o4 + i) * 4 + pp, t4[i]);
            }
            __syncwarp();
        }

        // MLP: fa starts at residual + fc2 bias; xr reused as hidden quarter
        {
            ull fa[16];
            {
                float4 fb = ldg4(fc2_b + l * 128 + o4);
                ull b2[4] = {dup2(fb.x), dup2(fb.y), dup2(fb.z), dup2(fb.w)};
#pragma unroll
                for (int pp = 0; pp < 4; ++pp)
#pragma unroll
                    for (int i = 0; i < 4; ++i)
                        fa[pp * 4 + i] = add2(ldp(xr, (o4 + i) * 4 + pp), b2[i]);
            }
#pragma unroll 1
            for (int qtr = 0; qtr < 4; ++qtr) {
                ull f1[16];
                bias16(fc1_b + l * 512 + qtr * 128, o4, f1);
                mvN4<128, 512>(f1W + qtr * 128, sx, o4, f1);
                __syncwarp();   // fc2 readers of xr (prev qtr) done
#pragma unroll
                for (int i = 0; i < 4; ++i) {
                    st16(xr, (o4 + i) * 4 + 0, gelu_t2(f1[0 * 4 + i]), gelu_t2(f1[1 * 4 + i]));
                    st16(xr, (o4 + i) * 4 + 2, gelu_t2(f1[2 * 4 + i]), gelu_t2(f1[3 * 4 + i]));
                }
                __syncwarp();
                mvN4<128, 128>(f2W + qtr * 16384, xr, o4, fa);
            }
            __syncwarp();   // last fc2 readers done
#pragma unroll
            for (int i = 0; i < 4; ++i) {
                st16(xr, (o4 + i) * 4 + 0, fa[0 * 4 + i], fa[1 * 4 + i]);
                st16(xr, (o4 + i) * 4 + 2, fa[2 * 4 + i], fa[3 * 4 + i]);
            }
        }
    }

    // ---- final head
    {
        // xf = LN(x) -> sx
        __syncwarp();
#pragma unroll
        for (int pp = 0; pp < 4; ++pp) {
            ull v4[4], t4[4];
#pragma unroll
            for (int i = 0; i < 4; ++i) v4[i] = ldp(xr, (o4 + i) * 4 + pp);
            ln2(v4, 1e-6f, t4);
#pragma unroll
            for (int i = 0; i < 4; ++i) stp(sx, (o4 + i) * 4 + pp, t4[i]);
        }
        __syncwarp();

        ull s2[16];
#pragma unroll
        for (int t = 0; t < 16; ++t) s2[t] = zeroD;

#pragma unroll 1
        for (int r = 0; r < 3; ++r) {
            ull tb[16];
            bias16(out1_b + r * 128, o4, tb);
            mvN4<128, 384>(g_WA + r * 128, sx, o4, tb);
            float4 w2v = ldg4(out2_w + r * 128 + o4);
            ull wd4[4] = {dup2(w2v.x), dup2(w2v.y), dup2(w2v.z), dup2(w2v.w)};
#pragma unroll 1
            for (int j = 0; j < 4; ++j) {
                build(j, 1e-6f, idG, idB);
                ull us[8];
#pragma unroll
                for (int t = 0; t < 8; ++t) us[t] = zeroD;
                mvN2<128, 384>(g_WB + r * 128, cb, o4, us);
                float uf[4][4];
#pragma unroll
                for (int dp = 0; dp < 2; ++dp)
#pragma unroll
                    for (int i = 0; i < 4; ++i) up2(us[dp * 4 + i], uf[2 * dp][i], uf[2 * dp + 1][i]);
#pragma unroll
                for (int pp = 0; pp < 4; ++pp)
#pragma unroll
                    for (int i = 0; i < 4; ++i)
                        s2[j * 4 + pp] = fma2(gelu_e2(add2(tb[pp * 4 + i], dup2(uf[pp][i]))),
                                              wd4[i], s2[j * 4 + pp]);
            }
        }

        const float o2b = __ldg(out2_b);
#pragma unroll
        for (int pp = 0; pp < 4; ++pp)
#pragma unroll
            for (int j = 0; j < 4; ++j) {
                ull t = wsum2(s2[j * 4 + pp]);
                if (ln == 0) {
                    float a, bv; up2(t, a, bv);
                    sa[2 * pp][j] = a + o2b;
                    sa[2 * pp + 1][j] = bv + o2b;
                }
            }
        __syncwarp();

        {
            int px = ln >> 2, j = ln & 3;
            float l0 = sa[px][0], l1 = sa[px][1], l2 = sa[px][2], l3 = sa[px][3];
            float mx = fmaxf(fmaxf(l0, l1), fmaxf(l2, l3));
            float den = __expf(l0 - mx) + __expf(l1 - mx) + __expf(l2 - mx) + __expf(l3 - mx);
            float e = __expf(sa[px][j] - mx);
            out[(((size_t)b * 4 + j) * kHu + hu) * kWu + wu0 + px] = e / den;
        }
    }
}

extern "C" void kernel_launch(void* const* d_in, const int* in_sizes, int n_in,
                              void* d_out, int out_size) {
    const float* feat     = (const float*)d_in[0];
    const float* featup   = (const float*)d_in[1];
    const float* ctx_ln_b = (const float*)d_in[2];
    const float* q_w      = (const float*)d_in[3];
    const float* q_b      = (const float*)d_in[4];
    const float* k_w      = (const float*)d_in[5];
    const float* k_b      = (const float*)d_in[6];
    const float* v_w      = (const float*)d_in[7];
    const float* v_b      = (const float*)d_in[8];
    const float* o_w      = (const float*)d_in[9];
    const float* o_b      = (const float*)d_in[10];
    const float* fc1_w    = (const float*)d_in[11];
    const float* fc1_b    = (const float*)d_in[12];
    const float* fc2_w    = (const float*)d_in[13];
    const float* fc2_b    = (const float*)d_in[14];
    const float* out1_w   = (const float*)d_in[15];
    const float* out1_b   = (const float*)d_in[16];
    const float* out2_w   = (const float*)d_in[17];
    const float* out2_b   = (const float*)d_in[18];
    const float* ctx_ln_g = (const float*)d_in[19];

    prep_kernel<<<(128 * 384 + 255) / 256, 256>>>(out1_w);
    upsample_tf_kernel<<<kN / 16, 64>>>(
        feat, featup, ctx_ln_b, q_w, q_b, k_w, k_b, v_w, v_b, o_w, o_b,
        fc1_w, fc1_b, fc2_w, fc2_b, out1_b, out2_w, out2_b, ctx_ln_g,
        (float*)d_out);
}

// round 15
// speedup vs baseline: 1.4021x; 1.0508x over previous
#include <cuda_runtime.h>
#include <math.h>

typedef unsigned long long ull;

namespace {
constexpr int kB = 2, kC = 128, kHd = 64, kWd = 96, kHu = 128, kWu = 192;
constexpr int kN = kB * kHu * kWu;
constexpr int kHWd = kHd * kWd, kHWu = kHu * kWu;
}

__device__ float g_WA[128 * 384];
__device__ float g_WB[128 * 384];

__global__ void prep_kernel(const float* __restrict__ o1w) {
    int i = blockIdx.x * blockDim.x + threadIdx.x;
    if (i < 128 * 384) {
        int in = i / 384, o = i - in * 384;
        float w2 = o1w[(256 + in) * 384 + o];
        g_WA[i] = o1w[in * 384 + o] + w2;
        g_WB[i] = o1w[(128 + in) * 384 + o] - w2;
    }
}

// ---- packed f32x2 (SASS FFMA2, PTX-only) ----
__device__ __forceinline__ ull pk2(float a, float b) {
    ull r; asm("mov.b64 %0,{%1,%2};" : "=l"(r) : "f"(a), "f"(b)); return r;
}
__device__ __forceinline__ ull dup2(float a) { return pk2(a, a); }
__device__ __forceinline__ void up2(ull v, float& a, float& b) {
    asm("mov.b64 {%0,%1},%2;" : "=f"(a), "=f"(b) : "l"(v));
}
__device__ __forceinline__ ull fma2(ull a, ull b, ull c) {
    ull d; asm("fma.rn.f32x2 %0,%1,%2,%3;" : "=l"(d) : "l"(a), "l"(b), "l"(c)); return d;
}
__device__ __forceinline__ ull add2(ull a, ull b) {
    ull d; asm("add.rn.f32x2 %0,%1,%2;" : "=l"(d) : "l"(a), "l"(b)); return d;
}
__device__ __forceinline__ ull mul2(ull a, ull b) {
    ull d; asm("mul.rn.f32x2 %0,%1,%2;" : "=l"(d) : "l"(a), "l"(b)); return d;
}

// 8B-slot smem, XOR swizzle on bits [1:4) (bit0 kept -> 16B pairs stay intact)
__device__ __forceinline__ int swz(int s) { return s ^ ((s >> 4) & 14); }
__device__ __forceinline__ ull ldp(const float* b, int s) {
    return *reinterpret_cast<const ull*>(b + 2 * swz(s));
}
__device__ __forceinline__ void stp(float* b, int s, ull v) {
    *reinterpret_cast<ull*>(b + 2 * swz(s)) = v;
}
__device__ __forceinline__ ulonglong2 ld16(const float* b, int s) {  // s even
    return *reinterpret_cast<const ulonglong2*>(b + 2 * swz(s));
}
__device__ __forceinline__ void st16(float* b, int s, ull x, ull y) {  // s even
    *reinterpret_cast<ulonglong2*>(b + 2 * swz(s)) = make_ulonglong2(x, y);
}

__device__ __forceinline__ ull wsum2(ull v) {
#pragma unroll
    for (int o = 16; o; o >>= 1) v = add2(v, __shfl_xor_sync(0xffffffffu, v, o));
    return v;
}

// LN of 2 independent 128-ch vectors packed as a pair: v[i] = ch (o4+i)
__device__ __forceinline__ void ln2(const ull v[4], float eps, ull o[4]) {
    ull s = add2(add2(v[0], v[1]), add2(v[2], v[3]));
    ull q = fma2(v[0], v[0], fma2(v[1], v[1], fma2(v[2], v[2], mul2(v[3], v[3]))));
    s = wsum2(s); q = wsum2(q);
    float s0, s1, q0, q1; up2(s, s0, s1); up2(q, q0, q1);
    float m0 = s0 * (1.0f / 128.0f), m1 = s1 * (1.0f / 128.0f);
    float r0 = rsqrtf(fmaxf(q0 * (1.0f / 128.0f) - m0 * m0, 0.0f) + eps);
    float r1 = rsqrtf(fmaxf(q1 * (1.0f / 128.0f) - m1 * m1, 0.0f) + eps);
    ull nm = pk2(-m0, -m1), rr = pk2(r0, r1);
#pragma unroll
    for (int i = 0; i < 4; ++i) o[i] = mul2(add2(v[i], nm), rr);
}

// fast tanh-gelu: x * sigmoid(2u), u = 0.79788456(x + 0.044715 x^3)
__device__ __forceinline__ float gelu_t(float x) {
    float x2 = x * x;
    float arg = -1.5957691216057308f * fmaf(0.044715f * x2, x, x);
    return __fdividef(x, 1.0f + __expf(arg));
}
__device__ __forceinline__ ull gelu_t2(ull v) { float a, b; up2(v, a, b); return pk2(gelu_t(a), gelu_t(b)); }
__device__ __forceinline__ float gelu_e(float x) { return 0.5f * x * (1.0f + erff(x * 0.7071067811865475f)); }
__device__ __forceinline__ ull gelu_e2(ull v) { float a, b; up2(v, a, b); return pk2(gelu_e(a), gelu_e(b)); }

__device__ __forceinline__ float4 ldg4(const float* p) {
    return __ldg(reinterpret_cast<const float4*>(p));
}

// GEMV over 4 pixel-pairs (8 px): acc[pp*4+i] += act[pp][in] * W[in*STRIDE+o4+i]
template <int NIN, int STRIDE>
__device__ __forceinline__ void mvN4(const float* __restrict__ W,
                                     const float* __restrict__ act, int o4, ull* acc) {
#pragma unroll 8
    for (int in = 0; in < NIN; ++in) {
        ulonglong2 A = ld16(act, in * 4), B = ld16(act, in * 4 + 2);
        float4 wv = ldg4(W + in * STRIDE + o4);
        ull w0 = dup2(wv.x), w1 = dup2(wv.y), w2 = dup2(wv.z), w3 = dup2(wv.w);
        acc[0]  = fma2(A.x, w0, acc[0]);  acc[1]  = fma2(A.x, w1, acc[1]);
        acc[2]  = fma2(A.x, w2, acc[2]);  acc[3]  = fma2(A.x, w3, acc[3]);
        acc[4]  = fma2(A.y, w0, acc[4]);  acc[5]  = fma2(A.y, w1, acc[5]);
        acc[6]  = fma2(A.y, w2, acc[6]);  acc[7]  = fma2(A.y, w3, acc[7]);
        acc[8]  = fma2(B.x, w0, acc[8]);  acc[9]  = fma2(B.x, w1, acc[9]);
        acc[10] = fma2(B.x, w2, acc[10]); acc[11] = fma2(B.x, w3, acc[11]);
        acc[12] = fma2(B.y, w0, acc[12]); acc[13] = fma2(B.y, w1, acc[13]);
        acc[14] = fma2(B.y, w2, acc[14]); acc[15] = fma2(B.y, w3, acc[15]);
    }
}

// GEMV over TWO ctx rows at once (each row = 2 dpairs):
// acc[row*8 + dp*4 + i] += act_row[dp][in] * W[in*STRIDE+o4+i]
// row 0 lives at act, row 1 at act + 512 floats (slot offset +256, swizzle-compatible).
template <int NIN, int STRIDE>
__device__ __forceinline__ void mvN22(const float* __restrict__ W,
                                      const float* __restrict__ act, int o4, ull* acc) {
#pragma unroll 8
    for (int in = 0; in < NIN; ++in) {
        ulonglong2 A = ld16(act, in * 2);
        ulonglong2 C = ld16(act + 512, in * 2);
        float4 wv = ldg4(W + in * STRIDE + o4);
        ull w0 = dup2(wv.x), w1 = dup2(wv.y), w2 = dup2(wv.z), w3 = dup2(wv.w);
        acc[0]  = fma2(A.x, w0, acc[0]);  acc[1]  = fma2(A.x, w1, acc[1]);
        acc[2]  = fma2(A.x, w2, acc[2]);  acc[3]  = fma2(A.x, w3, acc[3]);
        acc[4]  = fma2(A.y, w0, acc[4]);  acc[5]  = fma2(A.y, w1, acc[5]);
        acc[6]  = fma2(A.y, w2, acc[6]);  acc[7]  = fma2(A.y, w3, acc[7]);
        acc[8]  = fma2(C.x, w0, acc[8]);  acc[9]  = fma2(C.x, w1, acc[9]);
        acc[10] = fma2(C.x, w2, acc[10]); acc[11] = fma2(C.x, w3, acc[11]);
        acc[12] = fma2(C.y, w0, acc[12]); acc[13] = fma2(C.y, w1, acc[13]);
        acc[14] = fma2(C.y, w2, acc[14]); acc[15] = fma2(C.y, w3, acc[15]);
    }
}

__device__ __forceinline__ void bias16(const float* bp, int o4, ull* acc) {
    float4 b = ldg4(bp + o4);
    ull b2[4] = {dup2(b.x), dup2(b.y), dup2(b.z), dup2(b.w)};
#pragma unroll
    for (int p = 0; p < 4; ++p)
#pragma unroll
        for (int i = 0; i < 4; ++i) acc[p * 4 + i] = b2[i];
}

__device__ __forceinline__ void softmax4(float s[4]) {
    float mx = fmaxf(fmaxf(s[0], s[1]), fmaxf(s[2], s[3]));
    float e0 = __expf(s[0] - mx), e1 = __expf(s[1] - mx);
    float e2 = __expf(s[2] - mx), e3 = __expf(s[3] - mx);
    float inv = 1.0f / (e0 + e1 + e2 + e3);
    s[0] = e0 * inv; s[1] = e1 * inv; s[2] = e2 * inv; s[3] = e3 * inv;
}

__global__ __launch_bounds__(64, 8)
void upsample_tf_kernel(
    const float* __restrict__ feat, const float* __restrict__ featup,
    const float* __restrict__ ctx_ln_b,
    const float* __restrict__ q_w, const float* __restrict__ q_b,
    const float* __restrict__ k_w, const float* __restrict__ k_b,
    const float* __restrict__ v_w, const float* __restrict__ v_b,
    const float* __restrict__ o_w, const float* __restrict__ o_b,
    const float* __restrict__ fc1_w, const float* __restrict__ fc1_b,
    const float* __restrict__ fc2_w, const float* __restrict__ fc2_b,
    const float* __restrict__ out1_b,
    const float* __restrict__ out2_w, const float* __restrict__ out2_b,
    const float* __restrict__ ctx_ln_g,
    float* __restrict__ out)
{
    __shared__ __align__(16) float s_sx[2][1024];  // normed x-side vec (4 pairs)
    __shared__ __align__(16) float s_cb[2][1024];  // TWO ctx rows (2 dpairs each)
    __shared__ __align__(16) float s_xr[2][1024];  // residual / fc1-hidden quarter
    __shared__ float s_sa[2][8][4];

    const int w = threadIdx.x >> 5, ln = threadIdx.x & 31, o4 = ln * 4;
    const int n0 = (blockIdx.x * 2 + w) * 8;
    if (n0 >= kN) return;
    const int b = n0 / kHWu;
    const int rr = n0 - b * kHWu;
    const int hu = rr / kWu, wu0 = rr - hu * kWu;
    const int w0c = wu0 >> 1;                       // multiple of 4

    float* sx = s_sx[w];
    float* cb = s_cb[w];
    float* xr = s_xr[w];
    float (*sa)[4] = s_sa[w];

    const int rh0 = min(hu >> 1, kHd - 1), rh1 = min((hu >> 1) + 1, kHd - 1);
    const int hd = ln >> 3;
    const float slope = exp2f(-(float)(hd + 1) * 1.1462406251802891f);
    const float* fmb = feat + ((size_t)b * kC) * kHWd;

    // gather ctx row j: 4 distinct down-cols -> 2 dpairs, cv[dp*4+i]
    auto gather = [&](int j, ull cv[8]) {
        const int ky = j >> 1, kx = j & 1;
        const int rhv = ky ? rh1 : rh0;
#pragma unroll
        for (int i = 0; i < 4; ++i) {
            const float* cp = fmb + (size_t)(o4 + i) * kHWd + rhv * kWd;
            float4 q4 = ldg4(cp + w0c);
            float e = __ldg(cp + min(w0c + 4, kWd - 1));
            float d0, d1, d2, d3;
            if (kx == 0) { d0 = q4.x; d1 = q4.y; d2 = q4.z; d3 = q4.w; }
            else         { d0 = q4.y; d1 = q4.z; d2 = q4.w; d3 = e;    }
            cv[0 + i] = pk2(d0, d1);
            cv[4 + i] = pk2(d2, d3);
        }
    };
    // build LN'd ctx rows j0 and j0+1 into cb[0..511] and cb[512..1023]
    auto build2 = [&](int j0, float eps, const ull* gd, const ull* bd) {
        __syncwarp();   // previous cb readers done
#pragma unroll
        for (int r = 0; r < 2; ++r) {
            ull cv[8], t0[4], t1[4];
            gather(j0 + r, cv);
            ln2(cv + 0, eps, t0);
            ln2(cv + 4, eps, t1);
#pragma unroll
            for (int i = 0; i < 4; ++i)
                st16(cb + r * 512, (o4 + i) * 2,
                     fma2(t0[i], gd[i], bd[i]), fma2(t1[i], gd[i], bd[i]));
        }
        __syncwarp();
    };

    // ---- x load (8 px) -> residual xr (lane-private slots)
    {
        const float* fu = featup + ((size_t)b * kC) * kHWu + (size_t)hu * kWu + wu0;
#pragma unroll
        for (int i = 0; i < 4; ++i) {
            float4 A = ldg4(fu + (size_t)(o4 + i) * kHWu);
            float4 B = ldg4(fu + (size_t)(o4 + i) * kHWu + 4);
            st16(xr, (o4 + i) * 4 + 0, pk2(A.x, A.y), pk2(A.z, A.w));
            st16(xr, (o4 + i) * 4 + 2, pk2(B.x, B.y), pk2(B.z, B.w));
        }
    }

    const ull oneD = dup2(1.0f), zeroD = dup2(0.0f);
    const ull idG[4] = {oneD, oneD, oneD, oneD};
    const ull idB[4] = {zeroD, zeroD, zeroD, zeroD};

#pragma unroll 1
    for (int l = 0; l < 2; ++l) {
        const float* qW  = q_w  + l * 16384;
        const float* kW  = k_w  + l * 16384;
        const float* vW  = v_w  + l * 16384;
        const float* oW  = o_w  + l * 16384;
        const float* f1W = fc1_w + l * 65536;
        const float* f2W = fc2_w + l * 65536;

        ull gd[4], bd[4];
        {
            float4 gg = ldg4(ctx_ln_g + l * 128 + o4);
            float4 bb = ldg4(ctx_ln_b + l * 128 + o4);
            gd[0] = dup2(gg.x); gd[1] = dup2(gg.y); gd[2] = dup2(gg.z); gd[3] = dup2(gg.w);
            bd[0] = dup2(bb.x); bd[1] = dup2(bb.y); bd[2] = dup2(bb.z); bd[3] = dup2(bb.w);
        }

        // xn = LN(x) -> sx
        __syncwarp();
#pragma unroll
        for (int pp = 0; pp < 4; ++pp) {
            ull v4[4], t4[4];
#pragma unroll
            for (int i = 0; i < 4; ++i) v4[i] = ldp(xr, (o4 + i) * 4 + pp);
            ln2(v4, 1e-6f, t4);
#pragma unroll
            for (int i = 0; i < 4; ++i) stp(sx, (o4 + i) * 4 + pp, t4[i]);
        }
        __syncwarp();

        // q
        ull qa[16];
        bias16(q_b + l * 128, o4, qa);
        mvN4<128, 128>(qW, sx, o4, qa);

        // k: 2 rows per weight pass -> raw scores (pixel-paired)
        ull sc2[16];
        {
            float4 kbv = ldg4(k_b + l * 128 + o4);
#pragma unroll 1
            for (int jp = 0; jp < 4; jp += 2) {
                build2(jp, 1e-5f, gd, bd);
                ull ka[16];
                {
                    ull kb2[4] = {dup2(kbv.x), dup2(kbv.y), dup2(kbv.z), dup2(kbv.w)};
#pragma unroll
                    for (int t = 0; t < 16; ++t) ka[t] = kb2[t & 3];
                }
                mvN22<128, 128>(kW, cb, o4, ka);
#pragma unroll
                for (int r = 0; r < 2; ++r) {
                    int j = jp + r;
                    float kf[4][4];
#pragma unroll
                    for (int dp = 0; dp < 2; ++dp)
#pragma unroll
                        for (int i = 0; i < 4; ++i)
                            up2(ka[r * 8 + dp * 4 + i], kf[2 * dp][i], kf[2 * dp + 1][i]);
#pragma unroll
                    for (int pp = 0; pp < 4; ++pp) {
                        ull s = mul2(qa[pp * 4 + 0], dup2(kf[pp][0]));
                        s = fma2(qa[pp * 4 + 1], dup2(kf[pp][1]), s);
                        s = fma2(qa[pp * 4 + 2], dup2(kf[pp][2]), s);
                        s = fma2(qa[pp * 4 + 3], dup2(kf[pp][3]), s);
                        s = add2(s, __shfl_xor_sync(0xffffffffu, s, 1));
                        s = add2(s, __shfl_xor_sync(0xffffffffu, s, 2));
                        s = add2(s, __shfl_xor_sync(0xffffffffu, s, 4));
                        sc2[j * 4 + pp] = s;
                    }
                }
            }
        }

        // softmax + ALiBi per pixel
        ull a2[16];
#pragma unroll
        for (int pp = 0; pp < 4; ++pp) {
            float sA[4], sB[4];
#pragma unroll
            for (int j = 0; j < 4; ++j) {
                float pa, pb; up2(sc2[j * 4 + pp], pa, pb);
                const int ky = j >> 1, kx = j & 1;
                const int rhv = ky ? rh1 : rh0;
                int rwv = min(w0c + pp + kx, kWd - 1);
                float dyv = -(float)abs(hu - 2 * rhv);
                int wupA = wu0 + 2 * pp;
                float cdA = dyv - (float)abs(wupA - 2 * rwv);
                float cdB = dyv - (float)abs(wupA + 1 - 2 * rwv);
                sA[j] = pa * 0.17677669529663687f + slope * cdA;
                sB[j] = pb * 0.17677669529663687f + slope * cdB;
            }
            softmax4(sA); softmax4(sB);
#pragma unroll
            for (int j = 0; j < 4; ++j) a2[j * 4 + pp] = pk2(sA[j], sB[j]);
        }

        // v: 2 rows per weight pass -> ov
        ull ov[16];
#pragma unroll
        for (int t = 0; t < 16; ++t) ov[t] = zeroD;
        {
            float4 vbv = ldg4(v_b + l * 128 + o4);
#pragma unroll 1
            for (int jp = 0; jp < 4; jp += 2) {
                build2(jp, 1e-5f, gd, bd);
                ull va[16];
                {
                    ull vb2[4] = {dup2(vbv.x), dup2(vbv.y), dup2(vbv.z), dup2(vbv.w)};
#pragma unroll
                    for (int t = 0; t < 16; ++t) va[t] = vb2[t & 3];
                }
                mvN22<128, 128>(vW, cb, o4, va);
#pragma unroll
                for (int r = 0; r < 2; ++r) {
                    int j = jp + r;
                    float vf[4][4];
#pragma unroll
                    for (int dp = 0; dp < 2; ++dp)
#pragma unroll
                        for (int i = 0; i < 4; ++i)
                            up2(va[r * 8 + dp * 4 + i], vf[2 * dp][i], vf[2 * dp + 1][i]);
#pragma unroll
                    for (int pp = 0; pp < 4; ++pp)
#pragma unroll
                        for (int i = 0; i < 4; ++i)
                            ov[pp * 4 + i] = fma2(a2[j * 4 + pp], dup2(vf[pp][i]), ov[pp * 4 + i]);
                }
            }
        }

        // ov -> sx
        __syncwarp();
#pragma unroll
        for (int i = 0; i < 4; ++i) {
            st16(sx, (o4 + i) * 4 + 0, ov[0 * 4 + i], ov[1 * 4 + i]);
            st16(sx, (o4 + i) * 4 + 2, ov[2 * 4 + i], ov[3 * 4 + i]);
        }
        __syncwarp();

        // o-proj; x += ; hn = LN(x) -> sx
        {
            ull oa[16];
            bias16(o_b + l * 128, o4, oa);
            mvN4<128, 128>(oW, sx, o4, oa);
            __syncwarp();   // o-proj reads of sx done
#pragma unroll
            for (int pp = 0; pp < 4; ++pp) {
                ull v4[4], t4[4];
#pragma unroll
                for (int i = 0; i < 4; ++i) {
                    v4[i] = add2(ldp(xr, (o4 + i) * 4 + pp), oa[pp * 4 + i]);
                    stp(xr, (o4 + i) * 4 + pp, v4[i]);
                }
                ln2(v4, 1e-6f, t4);
#pragma unroll
                for (int i = 0; i < 4; ++i) stp(sx, (o4 + i) * 4 + pp, t4[i]);
            }
            __syncwarp();
        }

        // MLP: fa starts at residual + fc2 bias; xr reused as hidden quarter
        {
            ull fa[16];
            {
                float4 fb = ldg4(fc2_b + l * 128 + o4);
                ull b2[4] = {dup2(fb.x), dup2(fb.y), dup2(fb.z), dup2(fb.w)};
#pragma unroll
                for (int pp = 0; pp < 4; ++pp)
#pragma unroll
                    for (int i = 0; i < 4; ++i)
                        fa[pp * 4 + i] = add2(ldp(xr, (o4 + i) * 4 + pp), b2[i]);
            }
#pragma unroll 1
            for (int qtr = 0; qtr < 4; ++qtr) {
                ull f1[16];
                bias16(fc1_b + l * 512 + qtr * 128, o4, f1);
                mvN4<128, 512>(f1W + qtr * 128, sx, o4, f1);
                __syncwarp();   // fc2 readers of xr (prev qtr) done
#pragma unroll
                for (int i = 0; i < 4; ++i) {
                    st16(xr, (o4 + i) * 4 + 0, gelu_t2(f1[0 * 4 + i]), gelu_t2(f1[1 * 4 + i]));
                    st16(xr, (o4 + i) * 4 + 2, gelu_t2(f1[2 * 4 + i]), gelu_t2(f1[3 * 4 + i]));
                }
                __syncwarp();
                mvN4<128, 128>(f2W + qtr * 16384, xr, o4, fa);
            }
            __syncwarp();   // last fc2 readers done
#pragma unroll
            for (int i = 0; i < 4; ++i) {
                st16(xr, (o4 + i) * 4 + 0, fa[0 * 4 + i], fa[1 * 4 + i]);
                st16(xr, (o4 + i) * 4 + 2, fa[2 * 4 + i], fa[3 * 4 + i]);
            }
        }
    }

    // ---- final head
    {
        // xf = LN(x) -> sx
        __syncwarp();
#pragma unroll
        for (int pp = 0; pp < 4; ++pp) {
            ull v4[4], t4[4];
#pragma unroll
            for (int i = 0; i < 4; ++i) v4[i] = ldp(xr, (o4 + i) * 4 + pp);
            ln2(v4, 1e-6f, t4);
#pragma unroll
            for (int i = 0; i < 4; ++i) stp(sx, (o4 + i) * 4 + pp, t4[i]);
        }
        __syncwarp();

        ull s2[16];
#pragma unroll
        for (int t = 0; t < 16; ++t) s2[t] = zeroD;

#pragma unroll 1
        for (int r = 0; r < 3; ++r) {
            ull tb[16];
            bias16(out1_b + r * 128, o4, tb);
            mvN4<128, 384>(g_WA + r * 128, sx, o4, tb);
            float4 w2v = ldg4(out2_w + r * 128 + o4);
            ull wd4[4] = {dup2(w2v.x), dup2(w2v.y), dup2(w2v.z), dup2(w2v.w)};
#pragma unroll 1
            for (int jp = 0; jp < 4; jp += 2) {
                build2(jp, 1e-6f, idG, idB);
                ull us[16];
#pragma unroll
                for (int t = 0; t < 16; ++t) us[t] = zeroD;
                mvN22<128, 384>(g_WB + r * 128, cb, o4, us);
#pragma unroll
                for (int rw = 0; rw < 2; ++rw) {
                    int j = jp + rw;
                    float uf[4][4];
#pragma unroll
                    for (int dp = 0; dp < 2; ++dp)
#pragma unroll
                        for (int i = 0; i < 4; ++i)
                            up2(us[rw * 8 + dp * 4 + i], uf[2 * dp][i], uf[2 * dp + 1][i]);
#pragma unroll
                    for (int pp = 0; pp < 4; ++pp)
#pragma unroll
                        for (int i = 0; i < 4; ++i)
                            s2[j * 4 + pp] = fma2(gelu_e2(add2(tb[pp * 4 + i], dup2(uf[pp][i]))),
                                                  wd4[i], s2[j * 4 + pp]);
                }
            }
        }

        const float o2b = __ldg(out2_b);
#pragma unroll
        for (int pp = 0; pp < 4; ++pp)
#pragma unroll
            for (int j = 0; j < 4; ++j) {
                ull t = wsum2(s2[j * 4 + pp]);
                if (ln == 0) {
                    float a, bv; up2(t, a, bv);
                    sa[2 * pp][j] = a + o2b;
                    sa[2 * pp + 1][j] = bv + o2b;
                }
            }
        __syncwarp();

        {
            int px = ln >> 2, j = ln & 3;
            float l0 = sa[px][0], l1 = sa[px][1], l2 = sa[px][2], l3 = sa[px][3];
            float mx = fmaxf(fmaxf(l0, l1), fmaxf(l2, l3));
            float den = __expf(l0 - mx) + __expf(l1 - mx) + __expf(l2 - mx) + __expf(l3 - mx);
            float e = __expf(sa[px][j] - mx);
            out[(((size_t)b * 4 + j) * kHu + hu) * kWu + wu0 + px] = e / den;
        }
    }
}

extern "C" void kernel_launch(void* const* d_in, const int* in_sizes, int n_in,
                              void* d_out, int out_size) {
    const float* feat     = (const float*)d_in[0];
    const float* featup   = (const float*)d_in[1];
    const float* ctx_ln_b = (const float*)d_in[2];
    const float* q_w      = (const float*)d_in[3];
    const float* q_b      = (const float*)d_in[4];
    const float* k_w      = (const float*)d_in[5];
    const float* k_b      = (const float*)d_in[6];
    const float* v_w      = (const float*)d_in[7];
    const float* v_b      = (const float*)d_in[8];
    const float* o_w      = (const float*)d_in[9];
    const float* o_b      = (const float*)d_in[10];
    const float* fc1_w    = (const float*)d_in[11];
    const float* fc1_b    = (const float*)d_in[12];
    const float* fc2_w    = (const float*)d_in[13];
    const float* fc2_b    = (const float*)d_in[14];
    const float* out1_w   = (const float*)d_in[15];
    const float* out1_b   = (const float*)d_in[16];
    const float* out2_w   = (const float*)d_in[17];
    const float* out2_b   = (const float*)d_in[18];
    const float* ctx_ln_g = (const float*)d_in[19];

    prep_kernel<<<(128 * 384 + 255) / 256, 256>>>(out1_w);
    upsample_tf_kernel<<<kN / 16, 64>>>(
        feat, featup, ctx_ln_b, q_w, q_b, k_w, k_b, v_w, v_b, o_w, o_b,
        fc1_w, fc1_b, fc2_w, fc2_b, out1_b, out2_w, out2_b, ctx_ln_g,
        (float*)d_out);
}